// round 2
// baseline (speedup 1.0000x reference)
#include <cuda_runtime.h>

#define NN 50000
#define EE 800000
#define ET 850000          // EE + NN self loops
#define GG 50
#define FIN 64
#define HID 128
#define EMB 64
#define H1 8
#define C1 16
#define NCLS 6
#define EPSV 1e-5f
#define SLOPE 0.2f

// ---------------- scratch (static device globals; no allocation) ----------------
__device__ float g_deg[NN], g_asum[NN], g_loop[NN];
__device__ float g_xl1[NN * HID], g_xr1[NN * HID], g_out1[NN * HID], g_h1[NN * HID];
__device__ float g_exp1[ET * H1];
__device__ float g_s1[NN * H1];
__device__ float g_xl2[NN * EMB], g_xr2[NN * EMB], g_out2[NN * EMB];
__device__ float g_exp2[ET], g_s2[NN];
__device__ float g_bnsum[HID], g_bnsq[HID], g_scale[HID], g_shift[HID];
__device__ float g_pool[GG * EMB], g_cnt[GG], g_dom[GG * EMB];

// ---------------- kernels ----------------

__global__ void k_zero() {
    long long i0 = (long long)blockIdx.x * blockDim.x + threadIdx.x;
    long long st = (long long)gridDim.x * blockDim.x;
    for (long long i = i0; i < (long long)NN * HID; i += st) g_out1[i] = 0.f;
    for (long long i = i0; i < (long long)NN * EMB; i += st) g_out2[i] = 0.f;
    for (long long i = i0; i < (long long)NN * H1; i += st) g_s1[i] = 0.f;
    for (long long i = i0; i < NN; i += st) { g_deg[i] = 0.f; g_asum[i] = 0.f; g_s2[i] = 0.f; }
    for (long long i = i0; i < HID; i += st) { g_bnsum[i] = 0.f; g_bnsq[i] = 0.f; }
    for (long long i = i0; i < GG * EMB; i += st) g_pool[i] = 0.f;
    for (long long i = i0; i < GG; i += st) g_cnt[i] = 0.f;
}

__global__ void k_deg(const int* __restrict__ src, const int* __restrict__ dst,
                      const float* __restrict__ eattr) {
    int i = blockIdx.x * blockDim.x + threadIdx.x;
    if (i >= EE) return;
    int d = dst[i];
    atomicAdd(&g_deg[d], 1.f);
    atomicAdd(&g_asum[d], eattr[i]);
}

__global__ void k_loop() {
    int i = blockIdx.x * blockDim.x + threadIdx.x;
    if (i >= NN) return;
    float dg = g_deg[i];
    g_loop[i] = dg > 0.f ? g_asum[i] / dg : 0.f;
}

// Y[rows,kout] = X[rows,kin] @ W[kin,kout] + b
__global__ void k_linear(const float* __restrict__ X, const float* __restrict__ W,
                         const float* __restrict__ b, float* __restrict__ Y,
                         int rows, int kin, int kout) {
    extern __shared__ float sx[];
    const int ROWS = 16;
    int r0 = blockIdx.x * ROWS;
    int nrow = rows - r0; if (nrow > ROWS) nrow = ROWS;
    for (int idx = threadIdx.x; idx < nrow * kin; idx += blockDim.x)
        sx[idx] = X[(long long)r0 * kin + idx];
    __syncthreads();
    int col = threadIdx.x;
    float bias = b[col];
    for (int r = 0; r < nrow; r++) {
        float acc = 0.f;
        const float* xr = sx + r * kin;
#pragma unroll 8
        for (int k = 0; k < kin; k++)
            acc = fmaf(xr[k], W[k * kout + col], acc);
        Y[(long long)(r0 + r) * kout + col] = acc + bias;
    }
}

// layer 1: per edge (32 lanes, 4 channels each), 8 heads x 16 channels
__global__ void k_edge1(const int* __restrict__ src, const int* __restrict__ dst,
                        const float* __restrict__ eattr,
                        const float* __restrict__ We, const float* __restrict__ att) {
    int tid = blockIdx.x * blockDim.x + threadIdx.x;
    int e = tid >> 5;
    if (e >= ET) return;
    int lane = tid & 31;
    int s, d; float a;
    if (e < EE) { s = src[e]; d = dst[e]; a = eattr[e]; }
    else { s = e - EE; d = s; a = g_loop[s]; }
    int c0 = lane * 4;
    float4 xl = *(const float4*)(g_xl1 + s * HID + c0);
    float4 xr = *(const float4*)(g_xr1 + d * HID + c0);
    float4 we = *(const float4*)(We + c0);
    int h = lane >> 2;
    float4 at = *(const float4*)(att + h * C1 + (lane & 3) * 4);
    float t0 = xl.x + xr.x + a * we.x; t0 = t0 > 0.f ? t0 : SLOPE * t0;
    float t1 = xl.y + xr.y + a * we.y; t1 = t1 > 0.f ? t1 : SLOPE * t1;
    float t2 = xl.z + xr.z + a * we.z; t2 = t2 > 0.f ? t2 : SLOPE * t2;
    float t3 = xl.w + xr.w + a * we.w; t3 = t3 > 0.f ? t3 : SLOPE * t3;
    float p = t0 * at.x + t1 * at.y + t2 * at.z + t3 * at.w;
    p += __shfl_xor_sync(0xffffffffu, p, 1);
    p += __shfl_xor_sync(0xffffffffu, p, 2);
    if ((lane & 3) == 0) {
        float ex = expf(p);
        g_exp1[e * H1 + h] = ex;
        atomicAdd(&g_s1[d * H1 + h], ex);
    }
}

__global__ void k_scatter1(const int* __restrict__ src, const int* __restrict__ dst) {
    int tid = blockIdx.x * blockDim.x + threadIdx.x;
    int e = tid >> 5;
    if (e >= ET) return;
    int lane = tid & 31;
    int s, d;
    if (e < EE) { s = src[e]; d = dst[e]; }
    else { s = e - EE; d = s; }
    int h = lane >> 2;
    int c0 = lane * 4;
    float w = g_exp1[e * H1 + h] / g_s1[d * H1 + h];
    float4 xl = *(const float4*)(g_xl1 + s * HID + c0);
    float* o = g_out1 + d * HID + c0;
    atomicAdd(o + 0, xl.x * w);
    atomicAdd(o + 1, xl.y * w);
    atomicAdd(o + 2, xl.z * w);
    atomicAdd(o + 3, xl.w * w);
}

// layer 2: heads=1, 64 channels, 32 lanes x 2 channels
__global__ void k_edge2(const int* __restrict__ src, const int* __restrict__ dst,
                        const float* __restrict__ eattr,
                        const float* __restrict__ We, const float* __restrict__ att) {
    int tid = blockIdx.x * blockDim.x + threadIdx.x;
    int e = tid >> 5;
    if (e >= ET) return;
    int lane = tid & 31;
    int s, d; float a;
    if (e < EE) { s = src[e]; d = dst[e]; a = eattr[e]; }
    else { s = e - EE; d = s; a = g_loop[s]; }
    int c0 = lane * 2;
    float2 xl = *(const float2*)(g_xl2 + s * EMB + c0);
    float2 xr = *(const float2*)(g_xr2 + d * EMB + c0);
    float2 we = *(const float2*)(We + c0);
    float2 at = *(const float2*)(att + c0);
    float t0 = xl.x + xr.x + a * we.x; t0 = t0 > 0.f ? t0 : SLOPE * t0;
    float t1 = xl.y + xr.y + a * we.y; t1 = t1 > 0.f ? t1 : SLOPE * t1;
    float p = t0 * at.x + t1 * at.y;
#pragma unroll
    for (int off = 16; off > 0; off >>= 1)
        p += __shfl_xor_sync(0xffffffffu, p, off);
    if (lane == 0) {
        float ex = expf(p);
        g_exp2[e] = ex;
        atomicAdd(&g_s2[d], ex);
    }
}

__global__ void k_scatter2(const int* __restrict__ src, const int* __restrict__ dst) {
    int tid = blockIdx.x * blockDim.x + threadIdx.x;
    int e = tid >> 5;
    if (e >= ET) return;
    int lane = tid & 31;
    int s, d;
    if (e < EE) { s = src[e]; d = dst[e]; }
    else { s = e - EE; d = s; }
    float w = g_exp2[e] / g_s2[d];
    int c0 = lane * 2;
    float2 xl = *(const float2*)(g_xl2 + s * EMB + c0);
    float* o = g_out2 + d * EMB + c0;
    atomicAdd(o + 0, xl.x * w);
    atomicAdd(o + 1, xl.y * w);
}

// per-column sum / sumsq, blockDim.x == cols
__global__ void k_bnstats(const float* __restrict__ Y, int rows, int cols) {
    int col = threadIdx.x;
    int r0 = blockIdx.x * 256;
    int nr = rows - r0; if (nr > 256) nr = 256;
    float s = 0.f, q = 0.f;
    for (int r = 0; r < nr; r++) {
        float v = Y[(long long)(r0 + r) * cols + col];
        s += v; q += v * v;
    }
    atomicAdd(&g_bnsum[col], s);
    atomicAdd(&g_bnsq[col], q);
}

__global__ void k_bnfinal(const float* __restrict__ gamma, const float* __restrict__ beta,
                          int cols) {
    int c = threadIdx.x;
    if (c >= cols) return;
    float mu = g_bnsum[c] / (float)NN;
    float var = g_bnsq[c] / (float)NN - mu * mu;
    float sc = gamma[c] * rsqrtf(var + EPSV);
    g_scale[c] = sc;
    g_shift[c] = beta[c] - mu * sc;
    g_bnsum[c] = 0.f;  // reset for next BN layer
    g_bnsq[c] = 0.f;
}

__global__ void k_bnapply(const float* __restrict__ Yin, float* __restrict__ Yout,
                          int total, int cols) {
    int i = blockIdx.x * blockDim.x + threadIdx.x;
    if (i >= total) return;
    int c = i % cols;
    float v = Yin[i] * g_scale[c] + g_shift[c];
    Yout[i] = v > 0.f ? v : 0.f;
}

// layer-2 BN apply + relu + write node_emb + pooled sum
__global__ void k_bnapply2(const float* __restrict__ Yin, float* __restrict__ node_out,
                           const int* __restrict__ batch) {
    int i = blockIdx.x * blockDim.x + threadIdx.x;
    if (i >= NN * EMB) return;
    int c = i & (EMB - 1);
    int node = i >> 6;
    float v = Yin[i] * g_scale[c] + g_shift[c];
    v = v > 0.f ? v : 0.f;
    node_out[i] = v;
    atomicAdd(&g_pool[batch[node] * EMB + c], v);
}

__global__ void k_cnt(const int* __restrict__ batch) {
    int i = blockIdx.x * blockDim.x + threadIdx.x;
    if (i >= NN) return;
    atomicAdd(&g_cnt[batch[i]], 1.f);
}

__global__ void k_pool(float* __restrict__ out) {
    int i = blockIdx.x * blockDim.x + threadIdx.x;
    if (i >= GG * EMB) return;
    int g = i / EMB;
    float cnt = g_cnt[g];
    float dm = g_pool[i] / fmaxf(cnt, 1.f);
    g_dom[i] = dm;
    out[NCLS * GG + i] = dm;  // domain_emb region starts at 300
}

__global__ void k_logits(const float* __restrict__ Wc, const float* __restrict__ bc,
                         float* __restrict__ out) {
    int i = blockIdx.x * blockDim.x + threadIdx.x;
    if (i >= GG * NCLS) return;
    int g = i / NCLS, c = i % NCLS;
    float acc = bc[c];
    for (int k = 0; k < EMB; k++)
        acc = fmaf(g_dom[g * EMB + k], Wc[k * NCLS + c], acc);
    out[i] = acc;
}

// ---------------- host ----------------
extern "C" void kernel_launch(void* const* d_in, const int* in_sizes, int n_in,
                              void* d_out, int out_size) {
    const float* x     = (const float*)d_in[0];
    const int*   ei    = (const int*)d_in[1];
    const float* eattr = (const float*)d_in[2];
    const int*   batch = (const int*)d_in[3];
    const float* Wl1 = (const float*)d_in[4];  const float* bl1 = (const float*)d_in[5];
    const float* Wr1 = (const float*)d_in[6];  const float* br1 = (const float*)d_in[7];
    const float* We1 = (const float*)d_in[8];  const float* att1 = (const float*)d_in[9];
    // bias1 = d_in[10]: per-column constant, cancels exactly through BN -> skipped
    const float* Wl2 = (const float*)d_in[11]; const float* bl2 = (const float*)d_in[12];
    const float* Wr2 = (const float*)d_in[13]; const float* br2 = (const float*)d_in[14];
    const float* We2 = (const float*)d_in[15]; const float* att2 = (const float*)d_in[16];
    // bias2 = d_in[17]: cancels through BN2 -> skipped
    const float* gamma1 = (const float*)d_in[18]; const float* beta1 = (const float*)d_in[19];
    const float* gamma2 = (const float*)d_in[20]; const float* beta2 = (const float*)d_in[21];
    const float* Wc = (const float*)d_in[22]; const float* bc = (const float*)d_in[23];
    float* out = (float*)d_out;

    float *xl1, *xr1, *out1, *h1, *xl2, *xr2, *out2;
    cudaGetSymbolAddress((void**)&xl1, g_xl1);
    cudaGetSymbolAddress((void**)&xr1, g_xr1);
    cudaGetSymbolAddress((void**)&out1, g_out1);
    cudaGetSymbolAddress((void**)&h1, g_h1);
    cudaGetSymbolAddress((void**)&xl2, g_xl2);
    cudaGetSymbolAddress((void**)&xr2, g_xr2);
    cudaGetSymbolAddress((void**)&out2, g_out2);

    const int* src = ei;
    const int* dst = ei + EE;

    const int EB = (ET * 32 + 255) / 256;

    k_zero<<<2048, 256>>>();
    k_deg<<<(EE + 255) / 256, 256>>>(src, dst, eattr);
    k_loop<<<(NN + 255) / 256, 256>>>();

    k_linear<<<(NN + 15) / 16, HID, 16 * FIN * 4>>>(x, Wl1, bl1, xl1, NN, FIN, HID);
    k_linear<<<(NN + 15) / 16, HID, 16 * FIN * 4>>>(x, Wr1, br1, xr1, NN, FIN, HID);

    k_edge1<<<EB, 256>>>(src, dst, eattr, We1, att1);
    k_scatter1<<<EB, 256>>>(src, dst);

    k_bnstats<<<(NN + 255) / 256, HID>>>(out1, NN, HID);
    k_bnfinal<<<1, HID>>>(gamma1, beta1, HID);
    k_bnapply<<<(NN * HID + 255) / 256, 256>>>(out1, h1, NN * HID, HID);

    k_linear<<<(NN + 15) / 16, EMB, 16 * HID * 4>>>(h1, Wl2, bl2, xl2, NN, HID, EMB);
    k_linear<<<(NN + 15) / 16, EMB, 16 * HID * 4>>>(h1, Wr2, br2, xr2, NN, HID, EMB);

    k_edge2<<<EB, 256>>>(src, dst, eattr, We2, att2);
    k_scatter2<<<EB, 256>>>(src, dst);

    k_bnstats<<<(NN + 255) / 256, EMB>>>(out2, NN, EMB);
    k_bnfinal<<<1, EMB>>>(gamma2, beta2, EMB);
    k_cnt<<<(NN + 255) / 256, 256>>>(batch);
    k_bnapply2<<<(NN * EMB + 255) / 256, 256>>>(out2, out + NCLS * GG + GG * EMB, batch);
    k_pool<<<(GG * EMB + 255) / 256, 256>>>(out);
    k_logits<<<(GG * NCLS + 127) / 128, 128>>>(Wc, bc, out);
}

// round 3
// speedup vs baseline: 3.1846x; 3.1846x over previous
#include <cuda_runtime.h>

#define NN 50000
#define EE 800000
#define ET 850000          // EE + NN self loops
#define GG 50
#define FIN 64
#define HID 128
#define EMB 64
#define H1 8
#define C1 16
#define NCLS 6
#define EPSV 1e-5f
#define SLOPE 0.2f
#define NB 196             // ceil(NN/256)

// ---------------- scratch ----------------
__device__ int   g_ideg[NN], g_fill[NN], g_rowstart[NN];
__device__ int   g_psum[NB], g_poff[NB];
__device__ int   g_esrc[ET];
__device__ float g_eattrS[ET];
__device__ float g_asum[NN], g_loop[NN];
__device__ float g_xl1[NN * HID], g_xr1[NN * HID], g_out1[NN * HID], g_h1[NN * HID];
__device__ float g_xl2[NN * EMB], g_xr2[NN * EMB], g_out2[NN * EMB];
__device__ float g_bnsum[HID], g_bnsq[HID], g_scale[HID], g_shift[HID];
__device__ float g_pool[GG * EMB], g_cnt[GG], g_dom[GG * EMB];

// ---------------- setup kernels ----------------
__global__ void k_zero() {
    int i = blockIdx.x * blockDim.x + threadIdx.x;
    if (i < NN) { g_ideg[i] = 0; g_fill[i] = 0; g_asum[i] = 0.f; }
    if (i < HID) { g_bnsum[i] = 0.f; g_bnsq[i] = 0.f; }
    if (i < GG * EMB) g_pool[i] = 0.f;
    if (i < GG) g_cnt[i] = 0.f;
}

__global__ void k_hist(const int* __restrict__ dst, const float* __restrict__ eattr) {
    int i = blockIdx.x * blockDim.x + threadIdx.x;
    if (i >= EE) return;
    int d = dst[i];
    atomicAdd(&g_ideg[d], 1);
    atomicAdd(&g_asum[d], eattr[i]);
}

__global__ void k_loop() {
    int i = blockIdx.x * blockDim.x + threadIdx.x;
    if (i >= NN) return;
    int dg = g_ideg[i];
    g_loop[i] = dg > 0 ? g_asum[i] / (float)dg : 0.f;
}

__global__ void k_scanA() {
    __shared__ int s[256];
    int i = blockIdx.x * 256 + threadIdx.x;
    int v = (i < NN) ? g_ideg[i] + 1 : 0;
    s[threadIdx.x] = v; __syncthreads();
    for (int off = 128; off > 0; off >>= 1) {
        if (threadIdx.x < off) s[threadIdx.x] += s[threadIdx.x + off];
        __syncthreads();
    }
    if (threadIdx.x == 0) g_psum[blockIdx.x] = s[0];
}

__global__ void k_scanB() {
    __shared__ int s[256];
    int t = threadIdx.x;
    int v = (t < NB) ? g_psum[t] : 0;
    s[t] = v; __syncthreads();
    for (int off = 1; off < 256; off <<= 1) {
        int x = (t >= off) ? s[t - off] : 0;
        __syncthreads();
        s[t] += x;
        __syncthreads();
    }
    if (t < NB) g_poff[t] = s[t] - v;
}

// per-block exclusive scan + write rowstart + insert self-loop record (last slot)
__global__ void k_scanC() {
    __shared__ int s[256];
    int t = threadIdx.x;
    int i = blockIdx.x * 256 + t;
    int deg = (i < NN) ? g_ideg[i] : 0;
    int v = (i < NN) ? deg + 1 : 0;
    s[t] = v; __syncthreads();
    for (int off = 1; off < 256; off <<= 1) {
        int x = (t >= off) ? s[t - off] : 0;
        __syncthreads();
        s[t] += x;
        __syncthreads();
    }
    if (i < NN) {
        int rs = g_poff[blockIdx.x] + s[t] - v;
        g_rowstart[i] = rs;
        int pos = rs + deg;       // self loop is last slot
        g_esrc[pos] = i;
        g_eattrS[pos] = g_loop[i];
    }
}

__global__ void k_scatterE(const int* __restrict__ src, const int* __restrict__ dst,
                           const float* __restrict__ eattr) {
    int e = blockIdx.x * blockDim.x + threadIdx.x;
    if (e >= EE) return;
    int d = dst[e];
    int pos = g_rowstart[d] + atomicAdd(&g_fill[d], 1);
    g_esrc[pos] = src[e];
    g_eattrS[pos] = eattr[e];
}

// ---------------- register-tiled GEMM: Y = X @ W + b (two W/Y pairs per launch) ----------------
template<int KIN>
__global__ void k_gemm(const float* __restrict__ X, int rows,
                       const float* __restrict__ W1, const float* __restrict__ b1,
                       float* __restrict__ Y1,
                       const float* __restrict__ W2, const float* __restrict__ b2,
                       float* __restrict__ Y2,
                       int kout, int tiles1) {
    __shared__ float Xs[64][68];
    __shared__ float Ws[64][68];
    int yt = blockIdx.y;
    const float* W; const float* bb; float* Y; int colbase;
    if (yt < tiles1) { W = W1; bb = b1; Y = Y1; colbase = yt * 64; }
    else             { W = W2; bb = b2; Y = Y2; colbase = (yt - tiles1) * 64; }

    int tid = threadIdx.x;
    int tx = tid & 15, ty = tid >> 4;
    int r0 = blockIdx.x * 64;
    float acc[4][4] = {};

#pragma unroll
    for (int kt = 0; kt < KIN / 64; kt++) {
#pragma unroll
        for (int it = 0; it < 4; it++) {
            int r = ty + it * 16;
            int k4 = tx * 4;
            int row = r0 + r;
            float4 v = {0.f, 0.f, 0.f, 0.f};
            if (row < rows)
                v = *(const float4*)(X + (long long)row * KIN + kt * 64 + k4);
            *(float4*)&Xs[r][k4] = v;
        }
#pragma unroll
        for (int it = 0; it < 4; it++) {
            int k = ty + it * 16;
            int c4 = tx * 4;
            float4 v = *(const float4*)(W + (long long)(kt * 64 + k) * kout + colbase + c4);
            *(float4*)&Ws[k][c4] = v;
        }
        __syncthreads();
#pragma unroll
        for (int k = 0; k < 64; k++) {
            float a0 = Xs[ty * 4 + 0][k];
            float a1 = Xs[ty * 4 + 1][k];
            float a2 = Xs[ty * 4 + 2][k];
            float a3 = Xs[ty * 4 + 3][k];
            float4 bv = *(float4*)&Ws[k][tx * 4];
            acc[0][0] = fmaf(a0, bv.x, acc[0][0]); acc[0][1] = fmaf(a0, bv.y, acc[0][1]);
            acc[0][2] = fmaf(a0, bv.z, acc[0][2]); acc[0][3] = fmaf(a0, bv.w, acc[0][3]);
            acc[1][0] = fmaf(a1, bv.x, acc[1][0]); acc[1][1] = fmaf(a1, bv.y, acc[1][1]);
            acc[1][2] = fmaf(a1, bv.z, acc[1][2]); acc[1][3] = fmaf(a1, bv.w, acc[1][3]);
            acc[2][0] = fmaf(a2, bv.x, acc[2][0]); acc[2][1] = fmaf(a2, bv.y, acc[2][1]);
            acc[2][2] = fmaf(a2, bv.z, acc[2][2]); acc[2][3] = fmaf(a2, bv.w, acc[2][3]);
            acc[3][0] = fmaf(a3, bv.x, acc[3][0]); acc[3][1] = fmaf(a3, bv.y, acc[3][1]);
            acc[3][2] = fmaf(a3, bv.z, acc[3][2]); acc[3][3] = fmaf(a3, bv.w, acc[3][3]);
        }
        __syncthreads();
    }
    float4 bias = *(const float4*)(bb + colbase + tx * 4);
#pragma unroll
    for (int i = 0; i < 4; i++) {
        int row = r0 + ty * 4 + i;
        if (row < rows) {
            float4 o;
            o.x = acc[i][0] + bias.x; o.y = acc[i][1] + bias.y;
            o.z = acc[i][2] + bias.z; o.w = acc[i][3] + bias.w;
            *(float4*)(Y + (long long)row * kout + colbase + tx * 4) = o;
        }
    }
}

// ---------------- fused GATv2 aggregation: warp per node ----------------
__global__ void k_agg1(const float* __restrict__ We, const float* __restrict__ att) {
    int n = (blockIdx.x * blockDim.x + threadIdx.x) >> 5;
    if (n >= NN) return;
    int lane = threadIdx.x & 31;
    int start = g_rowstart[n];
    int end = start + g_ideg[n] + 1;
    int c0 = lane * 4;
    float4 xr = *(const float4*)(g_xr1 + (long long)n * HID + c0);
    float4 we = *(const float4*)(We + c0);
    int h = lane >> 2;
    float4 at = *(const float4*)(att + h * C1 + (lane & 3) * 4);
    float4 num = {0.f, 0.f, 0.f, 0.f};
    float den = 0.f;
    for (int e = start; e < end; e++) {
        int s = g_esrc[e];
        float a = g_eattrS[e];
        float4 xl = *(const float4*)(g_xl1 + (long long)s * HID + c0);
        float t0 = xl.x + xr.x + a * we.x; t0 = t0 > 0.f ? t0 : SLOPE * t0;
        float t1 = xl.y + xr.y + a * we.y; t1 = t1 > 0.f ? t1 : SLOPE * t1;
        float t2 = xl.z + xr.z + a * we.z; t2 = t2 > 0.f ? t2 : SLOPE * t2;
        float t3 = xl.w + xr.w + a * we.w; t3 = t3 > 0.f ? t3 : SLOPE * t3;
        float p = t0 * at.x + t1 * at.y + t2 * at.z + t3 * at.w;
        p += __shfl_xor_sync(0xffffffffu, p, 1);
        p += __shfl_xor_sync(0xffffffffu, p, 2);
        float ex = __expf(p);
        den += ex;
        num.x = fmaf(ex, xl.x, num.x);
        num.y = fmaf(ex, xl.y, num.y);
        num.z = fmaf(ex, xl.z, num.z);
        num.w = fmaf(ex, xl.w, num.w);
    }
    float inv = 1.f / den;
    float4 o = {num.x * inv, num.y * inv, num.z * inv, num.w * inv};
    *(float4*)(g_out1 + (long long)n * HID + c0) = o;
}

__global__ void k_agg2(const float* __restrict__ We, const float* __restrict__ att) {
    int n = (blockIdx.x * blockDim.x + threadIdx.x) >> 5;
    if (n >= NN) return;
    int lane = threadIdx.x & 31;
    int start = g_rowstart[n];
    int end = start + g_ideg[n] + 1;
    int c0 = lane * 2;
    float2 xr = *(const float2*)(g_xr2 + (long long)n * EMB + c0);
    float2 we = *(const float2*)(We + c0);
    float2 at = *(const float2*)(att + c0);
    float2 num = {0.f, 0.f};
    float den = 0.f;
    for (int e = start; e < end; e++) {
        int s = g_esrc[e];
        float a = g_eattrS[e];
        float2 xl = *(const float2*)(g_xl2 + (long long)s * EMB + c0);
        float t0 = xl.x + xr.x + a * we.x; t0 = t0 > 0.f ? t0 : SLOPE * t0;
        float t1 = xl.y + xr.y + a * we.y; t1 = t1 > 0.f ? t1 : SLOPE * t1;
        float p = t0 * at.x + t1 * at.y;
#pragma unroll
        for (int off = 16; off > 0; off >>= 1)
            p += __shfl_xor_sync(0xffffffffu, p, off);
        float ex = __expf(p);
        den += ex;
        num.x = fmaf(ex, xl.x, num.x);
        num.y = fmaf(ex, xl.y, num.y);
    }
    float inv = 1.f / den;
    float2 o = {num.x * inv, num.y * inv};
    *(float2*)(g_out2 + (long long)n * EMB + c0) = o;
}

// ---------------- BN / pooling / classifier ----------------
__global__ void k_bnstats(const float* __restrict__ Y, int rows, int cols) {
    int col = threadIdx.x;
    int r0 = blockIdx.x * 256;
    int nr = rows - r0; if (nr > 256) nr = 256;
    float s = 0.f, q = 0.f;
    for (int r = 0; r < nr; r++) {
        float v = Y[(long long)(r0 + r) * cols + col];
        s += v; q += v * v;
    }
    atomicAdd(&g_bnsum[col], s);
    atomicAdd(&g_bnsq[col], q);
}

__global__ void k_bnfinal(const float* __restrict__ gamma, const float* __restrict__ beta,
                          int cols) {
    int c = threadIdx.x;
    if (c >= cols) return;
    float mu = g_bnsum[c] / (float)NN;
    float var = g_bnsq[c] / (float)NN - mu * mu;
    float sc = gamma[c] * rsqrtf(var + EPSV);
    g_scale[c] = sc;
    g_shift[c] = beta[c] - mu * sc;
    g_bnsum[c] = 0.f;   // reset for next BN layer
    g_bnsq[c] = 0.f;
}

__global__ void k_bnapply(const float* __restrict__ Yin, float* __restrict__ Yout,
                          int total, int cols) {
    int i = blockIdx.x * blockDim.x + threadIdx.x;
    if (i >= total) return;
    int c = i % cols;
    float v = Yin[i] * g_scale[c] + g_shift[c];
    Yout[i] = v > 0.f ? v : 0.f;
}

__global__ void k_bnapply2(const float* __restrict__ Yin, float* __restrict__ node_out,
                           const int* __restrict__ batch) {
    int i = blockIdx.x * blockDim.x + threadIdx.x;
    if (i >= NN * EMB) return;
    int c = i & (EMB - 1);
    int node = i >> 6;
    float v = Yin[i] * g_scale[c] + g_shift[c];
    v = v > 0.f ? v : 0.f;
    node_out[i] = v;
    atomicAdd(&g_pool[batch[node] * EMB + c], v);
}

__global__ void k_cnt(const int* __restrict__ batch) {
    int i = blockIdx.x * blockDim.x + threadIdx.x;
    if (i >= NN) return;
    atomicAdd(&g_cnt[batch[i]], 1.f);
}

__global__ void k_pool(float* __restrict__ out) {
    int i = blockIdx.x * blockDim.x + threadIdx.x;
    if (i >= GG * EMB) return;
    int g = i / EMB;
    float dm = g_pool[i] / fmaxf(g_cnt[g], 1.f);
    g_dom[i] = dm;
    out[NCLS * GG + i] = dm;
}

__global__ void k_logits(const float* __restrict__ Wc, const float* __restrict__ bc,
                         float* __restrict__ out) {
    int i = blockIdx.x * blockDim.x + threadIdx.x;
    if (i >= GG * NCLS) return;
    int g = i / NCLS, c = i % NCLS;
    float acc = bc[c];
    for (int k = 0; k < EMB; k++)
        acc = fmaf(g_dom[g * EMB + k], Wc[k * NCLS + c], acc);
    out[i] = acc;
}

// ---------------- host ----------------
extern "C" void kernel_launch(void* const* d_in, const int* in_sizes, int n_in,
                              void* d_out, int out_size) {
    const float* x     = (const float*)d_in[0];
    const int*   ei    = (const int*)d_in[1];
    const float* eattr = (const float*)d_in[2];
    const int*   batch = (const int*)d_in[3];
    const float* Wl1 = (const float*)d_in[4];  const float* bl1 = (const float*)d_in[5];
    const float* Wr1 = (const float*)d_in[6];  const float* br1 = (const float*)d_in[7];
    const float* We1 = (const float*)d_in[8];  const float* att1 = (const float*)d_in[9];
    // bias1 (d_in[10]) cancels exactly through BN1 -> skipped
    const float* Wl2 = (const float*)d_in[11]; const float* bl2 = (const float*)d_in[12];
    const float* Wr2 = (const float*)d_in[13]; const float* br2 = (const float*)d_in[14];
    const float* We2 = (const float*)d_in[15]; const float* att2 = (const float*)d_in[16];
    // bias2 (d_in[17]) cancels through BN2 -> skipped
    const float* gamma1 = (const float*)d_in[18]; const float* beta1 = (const float*)d_in[19];
    const float* gamma2 = (const float*)d_in[20]; const float* beta2 = (const float*)d_in[21];
    const float* Wc = (const float*)d_in[22]; const float* bc = (const float*)d_in[23];
    float* out = (float*)d_out;

    float *xl1, *xr1, *out1, *h1, *xl2, *xr2, *out2;
    cudaGetSymbolAddress((void**)&xl1, g_xl1);
    cudaGetSymbolAddress((void**)&xr1, g_xr1);
    cudaGetSymbolAddress((void**)&out1, g_out1);
    cudaGetSymbolAddress((void**)&h1, g_h1);
    cudaGetSymbolAddress((void**)&xl2, g_xl2);
    cudaGetSymbolAddress((void**)&xr2, g_xr2);
    cudaGetSymbolAddress((void**)&out2, g_out2);

    const int* src = ei;
    const int* dst = ei + EE;

    // ---- CSR build ----
    k_zero<<<NB, 256>>>();
    k_hist<<<(EE + 255) / 256, 256>>>(dst, eattr);
    k_loop<<<NB, 256>>>();
    k_scanA<<<NB, 256>>>();
    k_scanB<<<1, 256>>>();
    k_scanC<<<NB, 256>>>();
    k_scatterE<<<(EE + 255) / 256, 256>>>(src, dst, eattr);

    // ---- layer 1 ----
    k_gemm<FIN><<<dim3(782, 4), 256>>>(x, NN, Wl1, bl1, xl1, Wr1, br1, xr1, HID, 2);
    k_agg1<<<(NN * 32 + 255) / 256, 256>>>(We1, att1);
    k_bnstats<<<NB, HID>>>(out1, NN, HID);
    k_bnfinal<<<1, HID>>>(gamma1, beta1, HID);
    k_bnapply<<<(NN * HID + 255) / 256, 256>>>(out1, h1, NN * HID, HID);

    // ---- layer 2 ----
    k_gemm<HID><<<dim3(782, 2), 256>>>(h1, NN, Wl2, bl2, xl2, Wr2, br2, xr2, EMB, 1);
    k_agg2<<<(NN * 32 + 255) / 256, 256>>>(We2, att2);
    k_bnstats<<<NB, EMB>>>(out2, NN, EMB);
    k_bnfinal<<<1, EMB>>>(gamma2, beta2, EMB);

    // ---- pooling + classifier ----
    k_cnt<<<NB, 256>>>(batch);
    k_bnapply2<<<(NN * EMB + 255) / 256, 256>>>(out2, out + NCLS * GG + GG * EMB, batch);
    k_pool<<<(GG * EMB + 255) / 256, 256>>>(out);
    k_logits<<<(GG * NCLS + 127) / 128, 128>>>(Wc, bc, out);
}

// round 4
// speedup vs baseline: 3.4305x; 1.0772x over previous
#include <cuda_runtime.h>

#define NN 50000
#define EE 800000
#define ET 850000          // EE + NN self loops
#define GG 50
#define FIN 64
#define HID 128
#define EMB 64
#define H1 8
#define C1 16
#define NCLS 6
#define EPSV 1e-5f
#define SLOPE 0.2f
#define NB 196             // ceil(NN/256)

// ---------------- scratch ----------------
__device__ int   g_ideg[NN], g_fill[NN], g_rowstart[NN];
__device__ int   g_psum[NB], g_poff[NB];
__device__ int   g_esrc[ET];
__device__ float g_eattrS[ET];
__device__ float g_asum[NN];
__device__ float g_xl1[NN * HID], g_xr1[NN * HID], g_out1[NN * HID];
__device__ float g_xl2[NN * EMB], g_xr2[NN * EMB], g_out2[NN * EMB];
__device__ float g_bnsum[HID], g_bnsq[HID], g_scale[HID], g_shift[HID];
__device__ float g_pool[GG * EMB], g_cnt[GG], g_dom[GG * EMB];

// ---------------- setup kernels ----------------
__global__ void k_zero() {
    int i = blockIdx.x * blockDim.x + threadIdx.x;
    if (i < NN) { g_ideg[i] = 0; g_fill[i] = 0; g_asum[i] = 0.f; }
    if (i < HID) { g_bnsum[i] = 0.f; g_bnsq[i] = 0.f; }
    if (i < GG * EMB) g_pool[i] = 0.f;
    if (i < GG) g_cnt[i] = 0.f;
}

__global__ void k_hist(const int* __restrict__ dst, const float* __restrict__ eattr) {
    int i = blockIdx.x * blockDim.x + threadIdx.x;
    if (i >= EE) return;
    int d = dst[i];
    atomicAdd(&g_ideg[d], 1);
    atomicAdd(&g_asum[d], eattr[i]);
}

__global__ void k_scanA() {
    __shared__ int s[256];
    int i = blockIdx.x * 256 + threadIdx.x;
    int v = (i < NN) ? g_ideg[i] + 1 : 0;
    s[threadIdx.x] = v; __syncthreads();
    for (int off = 128; off > 0; off >>= 1) {
        if (threadIdx.x < off) s[threadIdx.x] += s[threadIdx.x + off];
        __syncthreads();
    }
    if (threadIdx.x == 0) g_psum[blockIdx.x] = s[0];
}

__global__ void k_scanB() {
    __shared__ int s[256];
    int t = threadIdx.x;
    int v = (t < NB) ? g_psum[t] : 0;
    s[t] = v; __syncthreads();
    for (int off = 1; off < 256; off <<= 1) {
        int x = (t >= off) ? s[t - off] : 0;
        __syncthreads();
        s[t] += x;
        __syncthreads();
    }
    if (t < NB) g_poff[t] = s[t] - v;
}

// per-block exclusive scan + rowstart + self-loop record + batch counts
__global__ void k_scanC(const int* __restrict__ batch) {
    __shared__ int s[256];
    int t = threadIdx.x;
    int i = blockIdx.x * 256 + t;
    int deg = (i < NN) ? g_ideg[i] : 0;
    int v = (i < NN) ? deg + 1 : 0;
    s[t] = v; __syncthreads();
    for (int off = 1; off < 256; off <<= 1) {
        int x = (t >= off) ? s[t - off] : 0;
        __syncthreads();
        s[t] += x;
        __syncthreads();
    }
    if (i < NN) {
        int rs = g_poff[blockIdx.x] + s[t] - v;
        g_rowstart[i] = rs;
        int pos = rs + deg;       // self loop is last slot
        g_esrc[pos] = i;
        g_eattrS[pos] = deg > 0 ? g_asum[i] / (float)deg : 0.f;
        atomicAdd(&g_cnt[batch[i]], 1.f);
    }
}

__global__ void k_scatterE(const int* __restrict__ src, const int* __restrict__ dst,
                           const float* __restrict__ eattr) {
    int e = blockIdx.x * blockDim.x + threadIdx.x;
    if (e >= EE) return;
    int d = dst[e];
    int pos = g_rowstart[d] + atomicAdd(&g_fill[d], 1);
    g_esrc[pos] = src[e];
    g_eattrS[pos] = eattr[e];
}

// ---------------- register-tiled GEMM: Y = f(X) @ W + b (two W/Y pairs per launch) ----
// BN=true applies y = relu(x*scale + shift) to X elements while loading (fused BN1)
template<int KIN, bool BN>
__global__ void k_gemm(const float* __restrict__ X, int rows,
                       const float* __restrict__ W1, const float* __restrict__ b1,
                       float* __restrict__ Y1,
                       const float* __restrict__ W2, const float* __restrict__ b2,
                       float* __restrict__ Y2,
                       int kout, int tiles1) {
    __shared__ float Xs[64][68];
    __shared__ float Ws[64][68];
    int yt = blockIdx.y;
    const float* W; const float* bb; float* Y; int colbase;
    if (yt < tiles1) { W = W1; bb = b1; Y = Y1; colbase = yt * 64; }
    else             { W = W2; bb = b2; Y = Y2; colbase = (yt - tiles1) * 64; }

    int tid = threadIdx.x;
    int tx = tid & 15, ty = tid >> 4;
    int r0 = blockIdx.x * 64;
    float acc[4][4] = {};

#pragma unroll
    for (int kt = 0; kt < KIN / 64; kt++) {
#pragma unroll
        for (int it = 0; it < 4; it++) {
            int r = ty + it * 16;
            int k4 = tx * 4;
            int row = r0 + r;
            float4 v = {0.f, 0.f, 0.f, 0.f};
            if (row < rows)
                v = *(const float4*)(X + (long long)row * KIN + kt * 64 + k4);
            if (BN) {
                float4 sc = *(const float4*)(g_scale + kt * 64 + k4);
                float4 sh = *(const float4*)(g_shift + kt * 64 + k4);
                v.x = fmaxf(fmaf(v.x, sc.x, sh.x), 0.f);
                v.y = fmaxf(fmaf(v.y, sc.y, sh.y), 0.f);
                v.z = fmaxf(fmaf(v.z, sc.z, sh.z), 0.f);
                v.w = fmaxf(fmaf(v.w, sc.w, sh.w), 0.f);
            }
            *(float4*)&Xs[r][k4] = v;
        }
#pragma unroll
        for (int it = 0; it < 4; it++) {
            int k = ty + it * 16;
            int c4 = tx * 4;
            float4 v = *(const float4*)(W + (long long)(kt * 64 + k) * kout + colbase + c4);
            *(float4*)&Ws[k][c4] = v;
        }
        __syncthreads();
#pragma unroll
        for (int k = 0; k < 64; k++) {
            float a0 = Xs[ty * 4 + 0][k];
            float a1 = Xs[ty * 4 + 1][k];
            float a2 = Xs[ty * 4 + 2][k];
            float a3 = Xs[ty * 4 + 3][k];
            float4 bv = *(float4*)&Ws[k][tx * 4];
            acc[0][0] = fmaf(a0, bv.x, acc[0][0]); acc[0][1] = fmaf(a0, bv.y, acc[0][1]);
            acc[0][2] = fmaf(a0, bv.z, acc[0][2]); acc[0][3] = fmaf(a0, bv.w, acc[0][3]);
            acc[1][0] = fmaf(a1, bv.x, acc[1][0]); acc[1][1] = fmaf(a1, bv.y, acc[1][1]);
            acc[1][2] = fmaf(a1, bv.z, acc[1][2]); acc[1][3] = fmaf(a1, bv.w, acc[1][3]);
            acc[2][0] = fmaf(a2, bv.x, acc[2][0]); acc[2][1] = fmaf(a2, bv.y, acc[2][1]);
            acc[2][2] = fmaf(a2, bv.z, acc[2][2]); acc[2][3] = fmaf(a2, bv.w, acc[2][3]);
            acc[3][0] = fmaf(a3, bv.x, acc[3][0]); acc[3][1] = fmaf(a3, bv.y, acc[3][1]);
            acc[3][2] = fmaf(a3, bv.z, acc[3][2]); acc[3][3] = fmaf(a3, bv.w, acc[3][3]);
        }
        __syncthreads();
    }
    float4 bias = *(const float4*)(bb + colbase + tx * 4);
#pragma unroll
    for (int i = 0; i < 4; i++) {
        int row = r0 + ty * 4 + i;
        if (row < rows) {
            float4 o;
            o.x = acc[i][0] + bias.x; o.y = acc[i][1] + bias.y;
            o.z = acc[i][2] + bias.z; o.w = acc[i][3] + bias.w;
            *(float4*)(Y + (long long)row * kout + colbase + tx * 4) = o;
        }
    }
}

// ---------------- fused GATv2 aggregation: warp per node, 2-edge pipeline --------
__global__ void k_agg1(const float* __restrict__ We, const float* __restrict__ att) {
    int n = (blockIdx.x * blockDim.x + threadIdx.x) >> 5;
    if (n >= NN) return;
    int lane = threadIdx.x & 31;
    int start = g_rowstart[n];
    int end = start + g_ideg[n] + 1;
    int c0 = lane * 4;
    float4 xr = *(const float4*)(g_xr1 + (long long)n * HID + c0);
    float4 we = *(const float4*)(We + c0);
    int h = lane >> 2;
    float4 at = *(const float4*)(att + h * C1 + (lane & 3) * 4);
    float4 numA = {0.f, 0.f, 0.f, 0.f}, numB = {0.f, 0.f, 0.f, 0.f};
    float denA = 0.f, denB = 0.f;
    int e = start;
    for (; e + 1 < end; e += 2) {
        int s0 = g_esrc[e], s1 = g_esrc[e + 1];
        float a0 = g_eattrS[e], a1 = g_eattrS[e + 1];
        float4 x0 = *(const float4*)(g_xl1 + (long long)s0 * HID + c0);
        float4 x1 = *(const float4*)(g_xl1 + (long long)s1 * HID + c0);
        float u0, u1, u2, u3, p0, p1;
        u0 = x0.x + xr.x + a0 * we.x; u0 = u0 > 0.f ? u0 : SLOPE * u0;
        u1 = x0.y + xr.y + a0 * we.y; u1 = u1 > 0.f ? u1 : SLOPE * u1;
        u2 = x0.z + xr.z + a0 * we.z; u2 = u2 > 0.f ? u2 : SLOPE * u2;
        u3 = x0.w + xr.w + a0 * we.w; u3 = u3 > 0.f ? u3 : SLOPE * u3;
        p0 = u0 * at.x + u1 * at.y + u2 * at.z + u3 * at.w;
        u0 = x1.x + xr.x + a1 * we.x; u0 = u0 > 0.f ? u0 : SLOPE * u0;
        u1 = x1.y + xr.y + a1 * we.y; u1 = u1 > 0.f ? u1 : SLOPE * u1;
        u2 = x1.z + xr.z + a1 * we.z; u2 = u2 > 0.f ? u2 : SLOPE * u2;
        u3 = x1.w + xr.w + a1 * we.w; u3 = u3 > 0.f ? u3 : SLOPE * u3;
        p1 = u0 * at.x + u1 * at.y + u2 * at.z + u3 * at.w;
        p0 += __shfl_xor_sync(0xffffffffu, p0, 1);
        p0 += __shfl_xor_sync(0xffffffffu, p0, 2);
        p1 += __shfl_xor_sync(0xffffffffu, p1, 1);
        p1 += __shfl_xor_sync(0xffffffffu, p1, 2);
        float e0 = __expf(p0), e1 = __expf(p1);
        denA += e0; denB += e1;
        numA.x = fmaf(e0, x0.x, numA.x); numA.y = fmaf(e0, x0.y, numA.y);
        numA.z = fmaf(e0, x0.z, numA.z); numA.w = fmaf(e0, x0.w, numA.w);
        numB.x = fmaf(e1, x1.x, numB.x); numB.y = fmaf(e1, x1.y, numB.y);
        numB.z = fmaf(e1, x1.z, numB.z); numB.w = fmaf(e1, x1.w, numB.w);
    }
    if (e < end) {
        int s0 = g_esrc[e];
        float a0 = g_eattrS[e];
        float4 x0 = *(const float4*)(g_xl1 + (long long)s0 * HID + c0);
        float u0, u1, u2, u3;
        u0 = x0.x + xr.x + a0 * we.x; u0 = u0 > 0.f ? u0 : SLOPE * u0;
        u1 = x0.y + xr.y + a0 * we.y; u1 = u1 > 0.f ? u1 : SLOPE * u1;
        u2 = x0.z + xr.z + a0 * we.z; u2 = u2 > 0.f ? u2 : SLOPE * u2;
        u3 = x0.w + xr.w + a0 * we.w; u3 = u3 > 0.f ? u3 : SLOPE * u3;
        float p0 = u0 * at.x + u1 * at.y + u2 * at.z + u3 * at.w;
        p0 += __shfl_xor_sync(0xffffffffu, p0, 1);
        p0 += __shfl_xor_sync(0xffffffffu, p0, 2);
        float e0 = __expf(p0);
        denA += e0;
        numA.x = fmaf(e0, x0.x, numA.x); numA.y = fmaf(e0, x0.y, numA.y);
        numA.z = fmaf(e0, x0.z, numA.z); numA.w = fmaf(e0, x0.w, numA.w);
    }
    float inv = 1.f / (denA + denB);
    float4 o = {(numA.x + numB.x) * inv, (numA.y + numB.y) * inv,
                (numA.z + numB.z) * inv, (numA.w + numB.w) * inv};
    *(float4*)(g_out1 + (long long)n * HID + c0) = o;
}

__global__ void k_agg2(const float* __restrict__ We, const float* __restrict__ att) {
    int n = (blockIdx.x * blockDim.x + threadIdx.x) >> 5;
    if (n >= NN) return;
    int lane = threadIdx.x & 31;
    int start = g_rowstart[n];
    int end = start + g_ideg[n] + 1;
    int c0 = lane * 2;
    float2 xr = *(const float2*)(g_xr2 + (long long)n * EMB + c0);
    float2 we = *(const float2*)(We + c0);
    float2 at = *(const float2*)(att + c0);
    float2 numA = {0.f, 0.f}, numB = {0.f, 0.f};
    float denA = 0.f, denB = 0.f;
    int e = start;
    for (; e + 1 < end; e += 2) {
        int s0 = g_esrc[e], s1 = g_esrc[e + 1];
        float a0 = g_eattrS[e], a1 = g_eattrS[e + 1];
        float2 x0 = *(const float2*)(g_xl2 + (long long)s0 * EMB + c0);
        float2 x1 = *(const float2*)(g_xl2 + (long long)s1 * EMB + c0);
        float u0, u1, p0, p1;
        u0 = x0.x + xr.x + a0 * we.x; u0 = u0 > 0.f ? u0 : SLOPE * u0;
        u1 = x0.y + xr.y + a0 * we.y; u1 = u1 > 0.f ? u1 : SLOPE * u1;
        p0 = u0 * at.x + u1 * at.y;
        u0 = x1.x + xr.x + a1 * we.x; u0 = u0 > 0.f ? u0 : SLOPE * u0;
        u1 = x1.y + xr.y + a1 * we.y; u1 = u1 > 0.f ? u1 : SLOPE * u1;
        p1 = u0 * at.x + u1 * at.y;
#pragma unroll
        for (int off = 16; off > 0; off >>= 1) {
            p0 += __shfl_xor_sync(0xffffffffu, p0, off);
            p1 += __shfl_xor_sync(0xffffffffu, p1, off);
        }
        float e0 = __expf(p0), e1 = __expf(p1);
        denA += e0; denB += e1;
        numA.x = fmaf(e0, x0.x, numA.x); numA.y = fmaf(e0, x0.y, numA.y);
        numB.x = fmaf(e1, x1.x, numB.x); numB.y = fmaf(e1, x1.y, numB.y);
    }
    if (e < end) {
        int s0 = g_esrc[e];
        float a0 = g_eattrS[e];
        float2 x0 = *(const float2*)(g_xl2 + (long long)s0 * EMB + c0);
        float u0, u1;
        u0 = x0.x + xr.x + a0 * we.x; u0 = u0 > 0.f ? u0 : SLOPE * u0;
        u1 = x0.y + xr.y + a0 * we.y; u1 = u1 > 0.f ? u1 : SLOPE * u1;
        float p0 = u0 * at.x + u1 * at.y;
#pragma unroll
        for (int off = 16; off > 0; off >>= 1)
            p0 += __shfl_xor_sync(0xffffffffu, p0, off);
        float e0 = __expf(p0);
        denA += e0;
        numA.x = fmaf(e0, x0.x, numA.x); numA.y = fmaf(e0, x0.y, numA.y);
    }
    float inv = 1.f / (denA + denB);
    float2 o = {(numA.x + numB.x) * inv, (numA.y + numB.y) * inv};
    *(float2*)(g_out2 + (long long)n * EMB + c0) = o;
}

// ---------------- BN / pooling / classifier ----------------
__global__ void k_bnstats(const float* __restrict__ Y, int rows, int cols) {
    int col = threadIdx.x;
    int r0 = blockIdx.x * 256;
    int nr = rows - r0; if (nr > 256) nr = 256;
    float s = 0.f, q = 0.f;
    for (int r = 0; r < nr; r++) {
        float v = Y[(long long)(r0 + r) * cols + col];
        s += v; q += v * v;
    }
    atomicAdd(&g_bnsum[col], s);
    atomicAdd(&g_bnsq[col], q);
}

__global__ void k_bnfinal(const float* __restrict__ gamma, const float* __restrict__ beta,
                          int cols) {
    int c = threadIdx.x;
    if (c >= cols) return;
    float mu = g_bnsum[c] / (float)NN;
    float var = g_bnsq[c] / (float)NN - mu * mu;
    float sc = gamma[c] * rsqrtf(var + EPSV);
    g_scale[c] = sc;
    g_shift[c] = beta[c] - mu * sc;
    g_bnsum[c] = 0.f;   // reset for next BN layer
    g_bnsq[c] = 0.f;
}

__global__ void k_bnapply2(const float* __restrict__ Yin, float* __restrict__ node_out,
                           const int* __restrict__ batch) {
    int i = blockIdx.x * blockDim.x + threadIdx.x;
    if (i >= NN * EMB) return;
    int c = i & (EMB - 1);
    int node = i >> 6;
    float v = Yin[i] * g_scale[c] + g_shift[c];
    v = v > 0.f ? v : 0.f;
    node_out[i] = v;
    atomicAdd(&g_pool[batch[node] * EMB + c], v);
}

__global__ void k_pool(float* __restrict__ out) {
    int i = blockIdx.x * blockDim.x + threadIdx.x;
    if (i >= GG * EMB) return;
    int g = i / EMB;
    float dm = g_pool[i] / fmaxf(g_cnt[g], 1.f);
    g_dom[i] = dm;
    out[NCLS * GG + i] = dm;
}

__global__ void k_logits(const float* __restrict__ Wc, const float* __restrict__ bc,
                         float* __restrict__ out) {
    int i = blockIdx.x * blockDim.x + threadIdx.x;
    if (i >= GG * NCLS) return;
    int g = i / NCLS, c = i % NCLS;
    float acc = bc[c];
    for (int k = 0; k < EMB; k++)
        acc = fmaf(g_dom[g * EMB + k], Wc[k * NCLS + c], acc);
    out[i] = acc;
}

// ---------------- host ----------------
extern "C" void kernel_launch(void* const* d_in, const int* in_sizes, int n_in,
                              void* d_out, int out_size) {
    const float* x     = (const float*)d_in[0];
    const int*   ei    = (const int*)d_in[1];
    const float* eattr = (const float*)d_in[2];
    const int*   batch = (const int*)d_in[3];
    const float* Wl1 = (const float*)d_in[4];  const float* bl1 = (const float*)d_in[5];
    const float* Wr1 = (const float*)d_in[6];  const float* br1 = (const float*)d_in[7];
    const float* We1 = (const float*)d_in[8];  const float* att1 = (const float*)d_in[9];
    // bias1 (d_in[10]) cancels exactly through BN1 -> skipped
    const float* Wl2 = (const float*)d_in[11]; const float* bl2 = (const float*)d_in[12];
    const float* Wr2 = (const float*)d_in[13]; const float* br2 = (const float*)d_in[14];
    const float* We2 = (const float*)d_in[15]; const float* att2 = (const float*)d_in[16];
    // bias2 (d_in[17]) cancels through BN2 -> skipped
    const float* gamma1 = (const float*)d_in[18]; const float* beta1 = (const float*)d_in[19];
    const float* gamma2 = (const float*)d_in[20]; const float* beta2 = (const float*)d_in[21];
    const float* Wc = (const float*)d_in[22]; const float* bc = (const float*)d_in[23];
    float* out = (float*)d_out;

    float *xl1, *xr1, *out1, *xl2, *xr2, *out2;
    cudaGetSymbolAddress((void**)&xl1, g_xl1);
    cudaGetSymbolAddress((void**)&xr1, g_xr1);
    cudaGetSymbolAddress((void**)&out1, g_out1);
    cudaGetSymbolAddress((void**)&xl2, g_xl2);
    cudaGetSymbolAddress((void**)&xr2, g_xr2);
    cudaGetSymbolAddress((void**)&out2, g_out2);

    const int* src = ei;
    const int* dst = ei + EE;

    // ---- CSR build ----
    k_zero<<<NB, 256>>>();
    k_hist<<<(EE + 255) / 256, 256>>>(dst, eattr);
    k_scanA<<<NB, 256>>>();
    k_scanB<<<1, 256>>>();
    k_scanC<<<NB, 256>>>(batch);
    k_scatterE<<<(EE + 255) / 256, 256>>>(src, dst, eattr);

    // ---- layer 1 ----
    k_gemm<FIN, false><<<dim3(782, 4), 256>>>(x, NN, Wl1, bl1, xl1, Wr1, br1, xr1, HID, 2);
    k_agg1<<<(NN * 32 + 255) / 256, 256>>>(We1, att1);
    k_bnstats<<<NB, HID>>>(out1, NN, HID);
    k_bnfinal<<<1, HID>>>(gamma1, beta1, HID);

    // ---- layer 2 (BN1 + relu fused into GEMM X load) ----
    k_gemm<HID, true><<<dim3(782, 2), 256>>>(out1, NN, Wl2, bl2, xl2, Wr2, br2, xr2, EMB, 1);
    k_agg2<<<(NN * 32 + 255) / 256, 256>>>(We2, att2);
    k_bnstats<<<NB, EMB>>>(out2, NN, EMB);
    k_bnfinal<<<1, EMB>>>(gamma2, beta2, EMB);

    // ---- pooling + classifier ----
    k_bnapply2<<<(NN * EMB + 255) / 256, 256>>>(out2, out + NCLS * GG + GG * EMB, batch);
    k_pool<<<(GG * EMB + 255) / 256, 256>>>(out);
    k_logits<<<(GG * NCLS + 127) / 128, 128>>>(Wc, bc, out);
}

// round 5
// speedup vs baseline: 3.6625x; 1.0676x over previous
#include <cuda_runtime.h>

#define NN 50000
#define EE 800000
#define ET 850000          // EE + NN self loops
#define GG 50
#define FIN 64
#define HID 128
#define EMB 64
#define H1 8
#define C1 16
#define NCLS 6
#define EPSV 1e-5f
#define SLOPE 0.2f
#define NB 196             // ceil(NN/256)

// ---------------- scratch ----------------
__device__ int   g_ideg[NN], g_fill[NN], g_rowstart[NN];
__device__ int   g_psum[NB], g_poff[NB];
__device__ int   g_esrc[ET];
__device__ float g_eattrS[ET];
__device__ float g_asum[NN];
__device__ float g_xl1[NN * HID], g_xr1[NN * HID], g_out1[NN * HID];
__device__ float g_xl2[NN * EMB], g_xr2[NN * EMB], g_out2[NN * EMB];
__device__ float g_bnsum[HID], g_bnsq[HID];
__device__ float g_bnsum2[EMB], g_bnsq2[EMB];
__device__ float g_pool[GG * EMB], g_cnt[GG], g_dom[GG * EMB];

// ---------------- streams (static init; no device memory alloc) ----------------
static cudaStream_t g_side = nullptr;
static cudaEvent_t g_evF = nullptr, g_evJ = nullptr;
static struct SInit {
    SInit() {
        if (cudaStreamCreateWithFlags(&g_side, cudaStreamNonBlocking) != cudaSuccess) {
            g_side = nullptr; return;
        }
        if (cudaEventCreateWithFlags(&g_evF, cudaEventDisableTiming) != cudaSuccess ||
            cudaEventCreateWithFlags(&g_evJ, cudaEventDisableTiming) != cudaSuccess) {
            g_side = nullptr;
        }
    }
} s_init;

// ---------------- setup kernels ----------------
__global__ void k_zero() {
    int i = blockIdx.x * blockDim.x + threadIdx.x;
    if (i < NN) { g_ideg[i] = 0; g_fill[i] = 0; g_asum[i] = 0.f; }
    if (i < HID) { g_bnsum[i] = 0.f; g_bnsq[i] = 0.f; }
    if (i < EMB) { g_bnsum2[i] = 0.f; g_bnsq2[i] = 0.f; }
    if (i < GG * EMB) g_pool[i] = 0.f;
    if (i < GG) g_cnt[i] = 0.f;
}

__global__ void k_hist(const int* __restrict__ dst, const float* __restrict__ eattr) {
    int i = blockIdx.x * blockDim.x + threadIdx.x;
    if (i >= EE) return;
    int d = dst[i];
    atomicAdd(&g_ideg[d], 1);
    atomicAdd(&g_asum[d], eattr[i]);
}

__global__ void k_scanA() {
    __shared__ int s[256];
    int i = blockIdx.x * 256 + threadIdx.x;
    int v = (i < NN) ? g_ideg[i] + 1 : 0;
    s[threadIdx.x] = v; __syncthreads();
    for (int off = 128; off > 0; off >>= 1) {
        if (threadIdx.x < off) s[threadIdx.x] += s[threadIdx.x + off];
        __syncthreads();
    }
    if (threadIdx.x == 0) g_psum[blockIdx.x] = s[0];
}

__global__ void k_scanB() {
    __shared__ int s[256];
    int t = threadIdx.x;
    int v = (t < NB) ? g_psum[t] : 0;
    s[t] = v; __syncthreads();
    for (int off = 1; off < 256; off <<= 1) {
        int x = (t >= off) ? s[t - off] : 0;
        __syncthreads();
        s[t] += x;
        __syncthreads();
    }
    if (t < NB) g_poff[t] = s[t] - v;
}

// per-block exclusive scan + rowstart + self-loop record + batch counts
__global__ void k_scanC(const int* __restrict__ batch) {
    __shared__ int s[256];
    int t = threadIdx.x;
    int i = blockIdx.x * 256 + t;
    int deg = (i < NN) ? g_ideg[i] : 0;
    int v = (i < NN) ? deg + 1 : 0;
    s[t] = v; __syncthreads();
    for (int off = 1; off < 256; off <<= 1) {
        int x = (t >= off) ? s[t - off] : 0;
        __syncthreads();
        s[t] += x;
        __syncthreads();
    }
    if (i < NN) {
        int rs = g_poff[blockIdx.x] + s[t] - v;
        g_rowstart[i] = rs;
        int pos = rs + deg;       // self loop is last slot
        g_esrc[pos] = i;
        g_eattrS[pos] = deg > 0 ? g_asum[i] / (float)deg : 0.f;
        atomicAdd(&g_cnt[batch[i]], 1.f);
    }
}

__global__ void k_scatterE(const int* __restrict__ src, const int* __restrict__ dst,
                           const float* __restrict__ eattr) {
    int e = blockIdx.x * blockDim.x + threadIdx.x;
    if (e >= EE) return;
    int d = dst[e];
    int pos = g_rowstart[d] + atomicAdd(&g_fill[d], 1);
    g_esrc[pos] = src[e];
    g_eattrS[pos] = eattr[e];
}

// ---------------- GEMM: BM=128, BN=64, 8x4/thread, KTILE=32 ------------------
// BN fuse: X elements pass through relu(x*scale+shift) with scale/shift derived
// from layer-1 BN sums (computed once into smem).
template<int KIN, bool BNF>
__global__ void k_gemm(const float* __restrict__ X,
                       const float* __restrict__ W1, const float* __restrict__ b1,
                       float* __restrict__ Y1,
                       const float* __restrict__ W2, const float* __restrict__ b2,
                       float* __restrict__ Y2,
                       int kout, int tiles1,
                       const float* __restrict__ gamma, const float* __restrict__ beta) {
    __shared__ float Xs[128][36];
    __shared__ float Ws[32][68];
    __shared__ float sscale[KIN], sshift[KIN];
    int tid = threadIdx.x;
    if (BNF) {
        if (tid < KIN) {
            float mu = g_bnsum[tid] * (1.f / NN);
            float var = g_bnsq[tid] * (1.f / NN) - mu * mu;
            float sc = gamma[tid] * rsqrtf(var + EPSV);
            sscale[tid] = sc;
            sshift[tid] = beta[tid] - mu * sc;
        }
        __syncthreads();
    }
    int yt = blockIdx.y;
    const float* W; const float* bb; float* Y; int colbase;
    if (yt < tiles1) { W = W1; bb = b1; Y = Y1; colbase = yt * 64; }
    else             { W = W2; bb = b2; Y = Y2; colbase = (yt - tiles1) * 64; }

    int tx = tid & 15, ty = tid >> 4;
    int r0 = blockIdx.x * 128;
    float acc[8][4] = {};

#pragma unroll
    for (int kt = 0; kt < KIN / 32; kt++) {
#pragma unroll
        for (int it = 0; it < 4; it++) {
            int idx = tid + it * 256;
            int row = idx >> 3, kc4 = (idx & 7) * 4;
            int grow = r0 + row;
            float4 v = {0.f, 0.f, 0.f, 0.f};
            if (grow < NN)
                v = *(const float4*)(X + (size_t)grow * KIN + kt * 32 + kc4);
            if (BNF) {
                int kc = kt * 32 + kc4;
                v.x = fmaxf(fmaf(v.x, sscale[kc + 0], sshift[kc + 0]), 0.f);
                v.y = fmaxf(fmaf(v.y, sscale[kc + 1], sshift[kc + 1]), 0.f);
                v.z = fmaxf(fmaf(v.z, sscale[kc + 2], sshift[kc + 2]), 0.f);
                v.w = fmaxf(fmaf(v.w, sscale[kc + 3], sshift[kc + 3]), 0.f);
            }
            *(float4*)&Xs[row][kc4] = v;
        }
#pragma unroll
        for (int it = 0; it < 2; it++) {
            int idx = tid + it * 256;
            int k = idx >> 4, c4 = (idx & 15) * 4;
            float4 v = *(const float4*)(W + (size_t)(kt * 32 + k) * kout + colbase + c4);
            *(float4*)&Ws[k][c4] = v;
        }
        __syncthreads();
#pragma unroll
        for (int k = 0; k < 32; k++) {
            float4 bv = *(float4*)&Ws[k][tx * 4];
#pragma unroll
            for (int i = 0; i < 8; i++) {
                float a = Xs[ty * 8 + i][k];
                acc[i][0] = fmaf(a, bv.x, acc[i][0]);
                acc[i][1] = fmaf(a, bv.y, acc[i][1]);
                acc[i][2] = fmaf(a, bv.z, acc[i][2]);
                acc[i][3] = fmaf(a, bv.w, acc[i][3]);
            }
        }
        __syncthreads();
    }
    float4 bias = *(const float4*)(bb + colbase + tx * 4);
#pragma unroll
    for (int i = 0; i < 8; i++) {
        int row = r0 + ty * 8 + i;
        if (row < NN) {
            float4 o = {acc[i][0] + bias.x, acc[i][1] + bias.y,
                        acc[i][2] + bias.z, acc[i][3] + bias.w};
            *(float4*)(Y + (size_t)row * kout + colbase + tx * 4) = o;
        }
    }
}

// ---------------- fused GATv2 aggregation + BN stats: warp/node, 4-edge batch ----
__global__ void k_agg1(const float* __restrict__ We, const float* __restrict__ att) {
    __shared__ float ssum[HID], ssq[HID];
    int t = threadIdx.x;
    if (t < HID) { ssum[t] = 0.f; ssq[t] = 0.f; }
    __syncthreads();
    int n = (blockIdx.x * blockDim.x + t) >> 5;   // grid exactly covers NN
    int lane = t & 31;
    int start = g_rowstart[n];
    int end = start + g_ideg[n] + 1;
    int c0 = lane * 4;
    float4 xr = *(const float4*)(g_xr1 + (size_t)n * HID + c0);
    float4 we = *(const float4*)(We + c0);
    int h = lane >> 2;
    float4 at = *(const float4*)(att + h * C1 + (lane & 3) * 4);
    float4 numA = {0.f, 0.f, 0.f, 0.f}, numB = {0.f, 0.f, 0.f, 0.f};
    float denA = 0.f, denB = 0.f;
    int e = start;
    for (; e + 3 < end; e += 4) {
        int s0 = g_esrc[e], s1 = g_esrc[e + 1], s2 = g_esrc[e + 2], s3 = g_esrc[e + 3];
        float a0 = g_eattrS[e], a1 = g_eattrS[e + 1], a2 = g_eattrS[e + 2], a3 = g_eattrS[e + 3];
        float4 x0 = *(const float4*)(g_xl1 + (size_t)s0 * HID + c0);
        float4 x1 = *(const float4*)(g_xl1 + (size_t)s1 * HID + c0);
        float4 x2 = *(const float4*)(g_xl1 + (size_t)s2 * HID + c0);
        float4 x3 = *(const float4*)(g_xl1 + (size_t)s3 * HID + c0);
        float u0, u1, u2, u3;
        u0 = x0.x + xr.x + a0 * we.x; u0 = u0 > 0.f ? u0 : SLOPE * u0;
        u1 = x0.y + xr.y + a0 * we.y; u1 = u1 > 0.f ? u1 : SLOPE * u1;
        u2 = x0.z + xr.z + a0 * we.z; u2 = u2 > 0.f ? u2 : SLOPE * u2;
        u3 = x0.w + xr.w + a0 * we.w; u3 = u3 > 0.f ? u3 : SLOPE * u3;
        float p0 = u0 * at.x + u1 * at.y + u2 * at.z + u3 * at.w;
        u0 = x1.x + xr.x + a1 * we.x; u0 = u0 > 0.f ? u0 : SLOPE * u0;
        u1 = x1.y + xr.y + a1 * we.y; u1 = u1 > 0.f ? u1 : SLOPE * u1;
        u2 = x1.z + xr.z + a1 * we.z; u2 = u2 > 0.f ? u2 : SLOPE * u2;
        u3 = x1.w + xr.w + a1 * we.w; u3 = u3 > 0.f ? u3 : SLOPE * u3;
        float p1 = u0 * at.x + u1 * at.y + u2 * at.z + u3 * at.w;
        u0 = x2.x + xr.x + a2 * we.x; u0 = u0 > 0.f ? u0 : SLOPE * u0;
        u1 = x2.y + xr.y + a2 * we.y; u1 = u1 > 0.f ? u1 : SLOPE * u1;
        u2 = x2.z + xr.z + a2 * we.z; u2 = u2 > 0.f ? u2 : SLOPE * u2;
        u3 = x2.w + xr.w + a2 * we.w; u3 = u3 > 0.f ? u3 : SLOPE * u3;
        float p2 = u0 * at.x + u1 * at.y + u2 * at.z + u3 * at.w;
        u0 = x3.x + xr.x + a3 * we.x; u0 = u0 > 0.f ? u0 : SLOPE * u0;
        u1 = x3.y + xr.y + a3 * we.y; u1 = u1 > 0.f ? u1 : SLOPE * u1;
        u2 = x3.z + xr.z + a3 * we.z; u2 = u2 > 0.f ? u2 : SLOPE * u2;
        u3 = x3.w + xr.w + a3 * we.w; u3 = u3 > 0.f ? u3 : SLOPE * u3;
        float p3 = u0 * at.x + u1 * at.y + u2 * at.z + u3 * at.w;
        p0 += __shfl_xor_sync(0xffffffffu, p0, 1);
        p1 += __shfl_xor_sync(0xffffffffu, p1, 1);
        p2 += __shfl_xor_sync(0xffffffffu, p2, 1);
        p3 += __shfl_xor_sync(0xffffffffu, p3, 1);
        p0 += __shfl_xor_sync(0xffffffffu, p0, 2);
        p1 += __shfl_xor_sync(0xffffffffu, p1, 2);
        p2 += __shfl_xor_sync(0xffffffffu, p2, 2);
        p3 += __shfl_xor_sync(0xffffffffu, p3, 2);
        float e0 = __expf(p0), e1 = __expf(p1), e2 = __expf(p2), e3 = __expf(p3);
        denA += e0 + e2; denB += e1 + e3;
        numA.x = fmaf(e0, x0.x, fmaf(e2, x2.x, numA.x));
        numA.y = fmaf(e0, x0.y, fmaf(e2, x2.y, numA.y));
        numA.z = fmaf(e0, x0.z, fmaf(e2, x2.z, numA.z));
        numA.w = fmaf(e0, x0.w, fmaf(e2, x2.w, numA.w));
        numB.x = fmaf(e1, x1.x, fmaf(e3, x3.x, numB.x));
        numB.y = fmaf(e1, x1.y, fmaf(e3, x3.y, numB.y));
        numB.z = fmaf(e1, x1.z, fmaf(e3, x3.z, numB.z));
        numB.w = fmaf(e1, x1.w, fmaf(e3, x3.w, numB.w));
    }
    for (; e < end; e++) {
        int s0 = g_esrc[e];
        float a0 = g_eattrS[e];
        float4 x0 = *(const float4*)(g_xl1 + (size_t)s0 * HID + c0);
        float u0, u1, u2, u3;
        u0 = x0.x + xr.x + a0 * we.x; u0 = u0 > 0.f ? u0 : SLOPE * u0;
        u1 = x0.y + xr.y + a0 * we.y; u1 = u1 > 0.f ? u1 : SLOPE * u1;
        u2 = x0.z + xr.z + a0 * we.z; u2 = u2 > 0.f ? u2 : SLOPE * u2;
        u3 = x0.w + xr.w + a0 * we.w; u3 = u3 > 0.f ? u3 : SLOPE * u3;
        float p0 = u0 * at.x + u1 * at.y + u2 * at.z + u3 * at.w;
        p0 += __shfl_xor_sync(0xffffffffu, p0, 1);
        p0 += __shfl_xor_sync(0xffffffffu, p0, 2);
        float e0 = __expf(p0);
        denA += e0;
        numA.x = fmaf(e0, x0.x, numA.x); numA.y = fmaf(e0, x0.y, numA.y);
        numA.z = fmaf(e0, x0.z, numA.z); numA.w = fmaf(e0, x0.w, numA.w);
    }
    float inv = 1.f / (denA + denB);
    float4 o = {(numA.x + numB.x) * inv, (numA.y + numB.y) * inv,
                (numA.z + numB.z) * inv, (numA.w + numB.w) * inv};
    *(float4*)(g_out1 + (size_t)n * HID + c0) = o;
    atomicAdd(&ssum[c0 + 0], o.x); atomicAdd(&ssq[c0 + 0], o.x * o.x);
    atomicAdd(&ssum[c0 + 1], o.y); atomicAdd(&ssq[c0 + 1], o.y * o.y);
    atomicAdd(&ssum[c0 + 2], o.z); atomicAdd(&ssq[c0 + 2], o.z * o.z);
    atomicAdd(&ssum[c0 + 3], o.w); atomicAdd(&ssq[c0 + 3], o.w * o.w);
    __syncthreads();
    if (t < HID) { atomicAdd(&g_bnsum[t], ssum[t]); atomicAdd(&g_bnsq[t], ssq[t]); }
}

__global__ void k_agg2(const float* __restrict__ We, const float* __restrict__ att) {
    __shared__ float ssum[EMB], ssq[EMB];
    int t = threadIdx.x;
    if (t < EMB) { ssum[t] = 0.f; ssq[t] = 0.f; }
    __syncthreads();
    int n = (blockIdx.x * blockDim.x + t) >> 5;
    int lane = t & 31;
    int start = g_rowstart[n];
    int end = start + g_ideg[n] + 1;
    int c0 = lane * 2;
    float2 xr = *(const float2*)(g_xr2 + (size_t)n * EMB + c0);
    float2 we = *(const float2*)(We + c0);
    float2 at = *(const float2*)(att + c0);
    float2 numA = {0.f, 0.f}, numB = {0.f, 0.f};
    float denA = 0.f, denB = 0.f;
    int e = start;
    for (; e + 3 < end; e += 4) {
        int s0 = g_esrc[e], s1 = g_esrc[e + 1], s2 = g_esrc[e + 2], s3 = g_esrc[e + 3];
        float a0 = g_eattrS[e], a1 = g_eattrS[e + 1], a2 = g_eattrS[e + 2], a3 = g_eattrS[e + 3];
        float2 x0 = *(const float2*)(g_xl2 + (size_t)s0 * EMB + c0);
        float2 x1 = *(const float2*)(g_xl2 + (size_t)s1 * EMB + c0);
        float2 x2 = *(const float2*)(g_xl2 + (size_t)s2 * EMB + c0);
        float2 x3 = *(const float2*)(g_xl2 + (size_t)s3 * EMB + c0);
        float u0, u1;
        u0 = x0.x + xr.x + a0 * we.x; u0 = u0 > 0.f ? u0 : SLOPE * u0;
        u1 = x0.y + xr.y + a0 * we.y; u1 = u1 > 0.f ? u1 : SLOPE * u1;
        float p0 = u0 * at.x + u1 * at.y;
        u0 = x1.x + xr.x + a1 * we.x; u0 = u0 > 0.f ? u0 : SLOPE * u0;
        u1 = x1.y + xr.y + a1 * we.y; u1 = u1 > 0.f ? u1 : SLOPE * u1;
        float p1 = u0 * at.x + u1 * at.y;
        u0 = x2.x + xr.x + a2 * we.x; u0 = u0 > 0.f ? u0 : SLOPE * u0;
        u1 = x2.y + xr.y + a2 * we.y; u1 = u1 > 0.f ? u1 : SLOPE * u1;
        float p2 = u0 * at.x + u1 * at.y;
        u0 = x3.x + xr.x + a3 * we.x; u0 = u0 > 0.f ? u0 : SLOPE * u0;
        u1 = x3.y + xr.y + a3 * we.y; u1 = u1 > 0.f ? u1 : SLOPE * u1;
        float p3 = u0 * at.x + u1 * at.y;
#pragma unroll
        for (int off = 16; off > 0; off >>= 1) {
            p0 += __shfl_xor_sync(0xffffffffu, p0, off);
            p1 += __shfl_xor_sync(0xffffffffu, p1, off);
            p2 += __shfl_xor_sync(0xffffffffu, p2, off);
            p3 += __shfl_xor_sync(0xffffffffu, p3, off);
        }
        float e0 = __expf(p0), e1 = __expf(p1), e2 = __expf(p2), e3 = __expf(p3);
        denA += e0 + e2; denB += e1 + e3;
        numA.x = fmaf(e0, x0.x, fmaf(e2, x2.x, numA.x));
        numA.y = fmaf(e0, x0.y, fmaf(e2, x2.y, numA.y));
        numB.x = fmaf(e1, x1.x, fmaf(e3, x3.x, numB.x));
        numB.y = fmaf(e1, x1.y, fmaf(e3, x3.y, numB.y));
    }
    for (; e < end; e++) {
        int s0 = g_esrc[e];
        float a0 = g_eattrS[e];
        float2 x0 = *(const float2*)(g_xl2 + (size_t)s0 * EMB + c0);
        float u0, u1;
        u0 = x0.x + xr.x + a0 * we.x; u0 = u0 > 0.f ? u0 : SLOPE * u0;
        u1 = x0.y + xr.y + a0 * we.y; u1 = u1 > 0.f ? u1 : SLOPE * u1;
        float p0 = u0 * at.x + u1 * at.y;
#pragma unroll
        for (int off = 16; off > 0; off >>= 1)
            p0 += __shfl_xor_sync(0xffffffffu, p0, off);
        float e0 = __expf(p0);
        denA += e0;
        numA.x = fmaf(e0, x0.x, numA.x); numA.y = fmaf(e0, x0.y, numA.y);
    }
    float inv = 1.f / (denA + denB);
    float2 o = {(numA.x + numB.x) * inv, (numA.y + numB.y) * inv};
    *(float2*)(g_out2 + (size_t)n * EMB + c0) = o;
    atomicAdd(&ssum[c0 + 0], o.x); atomicAdd(&ssq[c0 + 0], o.x * o.x);
    atomicAdd(&ssum[c0 + 1], o.y); atomicAdd(&ssq[c0 + 1], o.y * o.y);
    __syncthreads();
    if (t < EMB) { atomicAdd(&g_bnsum2[t], ssum[t]); atomicAdd(&g_bnsq2[t], ssq[t]); }
}

// BN2(inline) + relu + write node_emb + pooled sums
__global__ void k_bnapply2(const float* __restrict__ Yin, float* __restrict__ node_out,
                           const int* __restrict__ batch,
                           const float* __restrict__ gamma, const float* __restrict__ beta) {
    int i = blockIdx.x * blockDim.x + threadIdx.x;
    if (i >= NN * EMB) return;
    int c = i & (EMB - 1);
    int node = i >> 6;
    float mu = g_bnsum2[c] * (1.f / NN);
    float var = g_bnsq2[c] * (1.f / NN) - mu * mu;
    float sc = gamma[c] * rsqrtf(var + EPSV);
    float v = fmaf(Yin[i] - mu, sc, beta[c]);
    v = fmaxf(v, 0.f);
    node_out[i] = v;
    atomicAdd(&g_pool[batch[node] * EMB + c], v);
}

__global__ void k_poollogits(const float* __restrict__ Wc, const float* __restrict__ bc,
                             float* __restrict__ out) {
    int t = threadIdx.x;   // single block, 1024 threads
    for (int i = t; i < GG * EMB; i += blockDim.x) {
        int g = i >> 6;
        float dm = g_pool[i] / fmaxf(g_cnt[g], 1.f);
        g_dom[i] = dm;
        out[NCLS * GG + i] = dm;
    }
    __syncthreads();
    if (t < GG * NCLS) {
        int g = t / NCLS, c = t % NCLS;
        float acc = bc[c];
#pragma unroll 8
        for (int k = 0; k < EMB; k++)
            acc = fmaf(g_dom[g * EMB + k], Wc[k * NCLS + c], acc);
        out[t] = acc;
    }
}

// ---------------- host ----------------
extern "C" void kernel_launch(void* const* d_in, const int* in_sizes, int n_in,
                              void* d_out, int out_size) {
    const float* x     = (const float*)d_in[0];
    const int*   ei    = (const int*)d_in[1];
    const float* eattr = (const float*)d_in[2];
    const int*   batch = (const int*)d_in[3];
    const float* Wl1 = (const float*)d_in[4];  const float* bl1 = (const float*)d_in[5];
    const float* Wr1 = (const float*)d_in[6];  const float* br1 = (const float*)d_in[7];
    const float* We1 = (const float*)d_in[8];  const float* att1 = (const float*)d_in[9];
    // bias1 (d_in[10]) cancels exactly through BN1 -> skipped
    const float* Wl2 = (const float*)d_in[11]; const float* bl2 = (const float*)d_in[12];
    const float* Wr2 = (const float*)d_in[13]; const float* br2 = (const float*)d_in[14];
    const float* We2 = (const float*)d_in[15]; const float* att2 = (const float*)d_in[16];
    // bias2 (d_in[17]) cancels through BN2 -> skipped
    const float* gamma1 = (const float*)d_in[18]; const float* beta1 = (const float*)d_in[19];
    const float* gamma2 = (const float*)d_in[20]; const float* beta2 = (const float*)d_in[21];
    const float* Wc = (const float*)d_in[22]; const float* bc = (const float*)d_in[23];
    float* out = (float*)d_out;

    float *xl1, *xr1, *out1, *xl2, *xr2, *out2;
    cudaGetSymbolAddress((void**)&xl1, g_xl1);
    cudaGetSymbolAddress((void**)&xr1, g_xr1);
    cudaGetSymbolAddress((void**)&out1, g_out1);
    cudaGetSymbolAddress((void**)&xl2, g_xl2);
    cudaGetSymbolAddress((void**)&xr2, g_xr2);
    cudaGetSymbolAddress((void**)&out2, g_out2);

    const int* src = ei;
    const int* dst = ei + EE;

    bool par = (g_side != nullptr);

    // ---- fork: gemm1 (depends only on inputs) runs concurrent with CSR build ----
    if (par) {
        cudaEventRecord(g_evF, 0);
        cudaStreamWaitEvent(g_side, g_evF, 0);
    }
    k_gemm<FIN, false><<<dim3(391, 4), 256, 0, par ? g_side : 0>>>(
        x, Wl1, bl1, xl1, Wr1, br1, xr1, HID, 2, nullptr, nullptr);
    if (par) cudaEventRecord(g_evJ, g_side);

    // ---- CSR build (main stream) ----
    k_zero<<<NB, 256>>>();
    k_hist<<<(EE + 255) / 256, 256>>>(dst, eattr);
    k_scanA<<<NB, 256>>>();
    k_scanB<<<1, 256>>>();
    k_scanC<<<NB, 256>>>(batch);
    k_scatterE<<<(EE + 255) / 256, 256>>>(src, dst, eattr);

    // ---- join ----
    if (par) cudaStreamWaitEvent(0, g_evJ, 0);

    // ---- layer 1 aggregation (+BN1 stats) ----
    k_agg1<<<6250, 256>>>(We1, att1);

    // ---- layer 2 (BN1+relu fused into GEMM X load) ----
    k_gemm<HID, true><<<dim3(391, 2), 256>>>(
        out1, Wl2, bl2, xl2, Wr2, br2, xr2, EMB, 1, gamma1, beta1);
    k_agg2<<<6250, 256>>>(We2, att2);

    // ---- BN2 + pooling + classifier ----
    k_bnapply2<<<(NN * EMB + 255) / 256, 256>>>(out2, out + NCLS * GG + GG * EMB,
                                                batch, gamma2, beta2);
    k_poollogits<<<1, 1024>>>(Wc, bc, out);
}

// round 6
// speedup vs baseline: 3.7108x; 1.0132x over previous
#include <cuda_runtime.h>
#include <cuda_fp16.h>

#define NN 50000
#define EE 800000
#define ET 850000          // EE + NN self loops
#define GG 50
#define FIN 64
#define HID 128
#define EMB 64
#define H1 8
#define C1 16
#define NCLS 6
#define EPSV 1e-5f
#define SLOPE 0.2f
#define NB 196             // ceil(NN/256)

// ---------------- scratch ----------------
__device__ int    g_ideg[NN], g_fill[NN], g_rowstart[NN];
__device__ int    g_psum[NB], g_poff[NB];
__device__ int2   g_edge[ET];          // {src, attr bits}
__device__ float  g_asum[NN];
__device__ __half g_xl1h[NN * HID];
__device__ float  g_xr1[NN * HID], g_out1[NN * HID];
__device__ float  g_xl2[NN * EMB], g_xr2[NN * EMB], g_out2[NN * EMB];
__device__ float  g_bnsum[HID], g_bnsq[HID];
__device__ float  g_bnsum2[EMB], g_bnsq2[EMB];
__device__ float  g_pool[GG * EMB], g_cnt[GG], g_dom[GG * EMB];

// ---------------- streams (static init; no device memory alloc) ----------------
static cudaStream_t g_side = nullptr;
static cudaEvent_t g_evF = nullptr, g_evJ = nullptr;
static struct SInit {
    SInit() {
        if (cudaStreamCreateWithFlags(&g_side, cudaStreamNonBlocking) != cudaSuccess) {
            g_side = nullptr; return;
        }
        if (cudaEventCreateWithFlags(&g_evF, cudaEventDisableTiming) != cudaSuccess ||
            cudaEventCreateWithFlags(&g_evJ, cudaEventDisableTiming) != cudaSuccess) {
            g_side = nullptr;
        }
    }
} s_init;

// ---------------- setup kernels ----------------
__global__ void k_zero() {
    int i = blockIdx.x * blockDim.x + threadIdx.x;
    if (i < NN) { g_ideg[i] = 0; g_fill[i] = 0; g_asum[i] = 0.f; }
    if (i < HID) { g_bnsum[i] = 0.f; g_bnsq[i] = 0.f; }
    if (i < EMB) { g_bnsum2[i] = 0.f; g_bnsq2[i] = 0.f; }
    if (i < GG * EMB) g_pool[i] = 0.f;
    if (i < GG) g_cnt[i] = 0.f;
}

__global__ void k_hist(const int* __restrict__ dst, const float* __restrict__ eattr) {
    int i = blockIdx.x * blockDim.x + threadIdx.x;
    if (i >= EE) return;
    int d = dst[i];
    atomicAdd(&g_ideg[d], 1);
    atomicAdd(&g_asum[d], eattr[i]);
}

__global__ void k_scanA() {
    __shared__ int s[256];
    int i = blockIdx.x * 256 + threadIdx.x;
    int v = (i < NN) ? g_ideg[i] + 1 : 0;
    s[threadIdx.x] = v; __syncthreads();
    for (int off = 128; off > 0; off >>= 1) {
        if (threadIdx.x < off) s[threadIdx.x] += s[threadIdx.x + off];
        __syncthreads();
    }
    if (threadIdx.x == 0) g_psum[blockIdx.x] = s[0];
}

__global__ void k_scanB() {
    __shared__ int s[256];
    int t = threadIdx.x;
    int v = (t < NB) ? g_psum[t] : 0;
    s[t] = v; __syncthreads();
    for (int off = 1; off < 256; off <<= 1) {
        int x = (t >= off) ? s[t - off] : 0;
        __syncthreads();
        s[t] += x;
        __syncthreads();
    }
    if (t < NB) g_poff[t] = s[t] - v;
}

// per-block exclusive scan + rowstart + self-loop record + batch counts
__global__ void k_scanC(const int* __restrict__ batch) {
    __shared__ int s[256];
    int t = threadIdx.x;
    int i = blockIdx.x * 256 + t;
    int deg = (i < NN) ? g_ideg[i] : 0;
    int v = (i < NN) ? deg + 1 : 0;
    s[t] = v; __syncthreads();
    for (int off = 1; off < 256; off <<= 1) {
        int x = (t >= off) ? s[t - off] : 0;
        __syncthreads();
        s[t] += x;
        __syncthreads();
    }
    if (i < NN) {
        int rs = g_poff[blockIdx.x] + s[t] - v;
        g_rowstart[i] = rs;
        float la = deg > 0 ? g_asum[i] / (float)deg : 0.f;
        g_edge[rs + deg] = make_int2(i, __float_as_int(la));   // self loop last
        atomicAdd(&g_cnt[batch[i]], 1.f);
    }
}

__global__ void k_scatterE(const int* __restrict__ src, const int* __restrict__ dst,
                           const float* __restrict__ eattr) {
    int e = blockIdx.x * blockDim.x + threadIdx.x;
    if (e >= EE) return;
    int d = dst[e];
    int pos = g_rowstart[d] + atomicAdd(&g_fill[d], 1);
    g_edge[pos] = make_int2(src[e], __float_as_int(eattr[e]));
}

// ---------------- GEMM: BM=128, BN=64, 8x4/thread, KTILE=32 ------------------
// BNF: X passes through relu(x*scale+shift) (fused BN1). HOUT: Y1 written fp16.
template<int KIN, bool BNF, bool HOUT>
__global__ void k_gemm(const float* __restrict__ X,
                       const float* __restrict__ W1, const float* __restrict__ b1,
                       float* __restrict__ Y1, __half* __restrict__ Y1h,
                       const float* __restrict__ W2, const float* __restrict__ b2,
                       float* __restrict__ Y2,
                       int kout, int tiles1,
                       const float* __restrict__ gamma, const float* __restrict__ beta) {
    __shared__ float Xs[128][36];
    __shared__ float Ws[32][68];
    __shared__ float sscale[KIN], sshift[KIN];
    int tid = threadIdx.x;
    if (BNF) {
        if (tid < KIN) {
            float mu = g_bnsum[tid] * (1.f / NN);
            float var = g_bnsq[tid] * (1.f / NN) - mu * mu;
            float sc = gamma[tid] * rsqrtf(var + EPSV);
            sscale[tid] = sc;
            sshift[tid] = beta[tid] - mu * sc;
        }
        __syncthreads();
    }
    int yt = blockIdx.y;
    bool first = yt < tiles1;
    const float* W; const float* bb; int colbase;
    if (first) { W = W1; bb = b1; colbase = yt * 64; }
    else       { W = W2; bb = b2; colbase = (yt - tiles1) * 64; }

    int tx = tid & 15, ty = tid >> 4;
    int r0 = blockIdx.x * 128;
    float acc[8][4] = {};

#pragma unroll
    for (int kt = 0; kt < KIN / 32; kt++) {
#pragma unroll
        for (int it = 0; it < 4; it++) {
            int idx = tid + it * 256;
            int row = idx >> 3, kc4 = (idx & 7) * 4;
            int grow = r0 + row;
            float4 v = {0.f, 0.f, 0.f, 0.f};
            if (grow < NN)
                v = *(const float4*)(X + (size_t)grow * KIN + kt * 32 + kc4);
            if (BNF) {
                int kc = kt * 32 + kc4;
                v.x = fmaxf(fmaf(v.x, sscale[kc + 0], sshift[kc + 0]), 0.f);
                v.y = fmaxf(fmaf(v.y, sscale[kc + 1], sshift[kc + 1]), 0.f);
                v.z = fmaxf(fmaf(v.z, sscale[kc + 2], sshift[kc + 2]), 0.f);
                v.w = fmaxf(fmaf(v.w, sscale[kc + 3], sshift[kc + 3]), 0.f);
            }
            *(float4*)&Xs[row][kc4] = v;
        }
#pragma unroll
        for (int it = 0; it < 2; it++) {
            int idx = tid + it * 256;
            int k = idx >> 4, c4 = (idx & 15) * 4;
            float4 v = *(const float4*)(W + (size_t)(kt * 32 + k) * kout + colbase + c4);
            *(float4*)&Ws[k][c4] = v;
        }
        __syncthreads();
#pragma unroll
        for (int k = 0; k < 32; k++) {
            float4 bv = *(float4*)&Ws[k][tx * 4];
#pragma unroll
            for (int i = 0; i < 8; i++) {
                float a = Xs[ty * 8 + i][k];
                acc[i][0] = fmaf(a, bv.x, acc[i][0]);
                acc[i][1] = fmaf(a, bv.y, acc[i][1]);
                acc[i][2] = fmaf(a, bv.z, acc[i][2]);
                acc[i][3] = fmaf(a, bv.w, acc[i][3]);
            }
        }
        __syncthreads();
    }
    float4 bias = *(const float4*)(bb + colbase + tx * 4);
#pragma unroll
    for (int i = 0; i < 8; i++) {
        int row = r0 + ty * 8 + i;
        if (row < NN) {
            float4 o = {acc[i][0] + bias.x, acc[i][1] + bias.y,
                        acc[i][2] + bias.z, acc[i][3] + bias.w};
            if (HOUT && first) {
                __half2 h01 = __floats2half2_rn(o.x, o.y);
                __half2 h23 = __floats2half2_rn(o.z, o.w);
                __half2* p = (__half2*)(Y1h + (size_t)row * kout + colbase + tx * 4);
                p[0] = h01; p[1] = h23;
            } else {
                float* Y = first ? Y1 : Y2;
                *(float4*)(Y + (size_t)row * kout + colbase + tx * 4) = o;
            }
        }
    }
}

// ---------------- fused GATv2 aggregation + BN stats: warp/node, 4-edge batch ----
__device__ __forceinline__ void xl1_load(int s, int c0, float4& f) {
    uint2 raw = *(const uint2*)(g_xl1h + (size_t)s * HID + c0);
    float2 f01 = __half22float2(*(__half2*)&raw.x);
    float2 f23 = __half22float2(*(__half2*)&raw.y);
    f.x = f01.x; f.y = f01.y; f.z = f23.x; f.w = f23.y;
}

__global__ void k_agg1(const float* __restrict__ We, const float* __restrict__ att) {
    __shared__ float ssum[HID], ssq[HID];
    int t = threadIdx.x;
    if (t < HID) { ssum[t] = 0.f; ssq[t] = 0.f; }
    __syncthreads();
    int n = (blockIdx.x * blockDim.x + t) >> 5;   // grid exactly covers NN
    int lane = t & 31;
    int start = g_rowstart[n];
    int end = start + g_ideg[n] + 1;
    int c0 = lane * 4;
    float4 xr = *(const float4*)(g_xr1 + (size_t)n * HID + c0);
    float4 we = *(const float4*)(We + c0);
    int h = lane >> 2;
    float4 at = *(const float4*)(att + h * C1 + (lane & 3) * 4);
    float4 numA = {0.f, 0.f, 0.f, 0.f}, numB = {0.f, 0.f, 0.f, 0.f};
    float denA = 0.f, denB = 0.f;
    int e = start;
    for (; e + 3 < end; e += 4) {
        int2 e0 = g_edge[e], e1 = g_edge[e + 1], e2i = g_edge[e + 2], e3i = g_edge[e + 3];
        float a0 = __int_as_float(e0.y), a1 = __int_as_float(e1.y);
        float a2 = __int_as_float(e2i.y), a3 = __int_as_float(e3i.y);
        float4 x0, x1, x2, x3;
        xl1_load(e0.x, c0, x0);
        xl1_load(e1.x, c0, x1);
        xl1_load(e2i.x, c0, x2);
        xl1_load(e3i.x, c0, x3);
        float u0, u1, u2, u3;
        u0 = x0.x + xr.x + a0 * we.x; u0 = u0 > 0.f ? u0 : SLOPE * u0;
        u1 = x0.y + xr.y + a0 * we.y; u1 = u1 > 0.f ? u1 : SLOPE * u1;
        u2 = x0.z + xr.z + a0 * we.z; u2 = u2 > 0.f ? u2 : SLOPE * u2;
        u3 = x0.w + xr.w + a0 * we.w; u3 = u3 > 0.f ? u3 : SLOPE * u3;
        float p0 = u0 * at.x + u1 * at.y + u2 * at.z + u3 * at.w;
        u0 = x1.x + xr.x + a1 * we.x; u0 = u0 > 0.f ? u0 : SLOPE * u0;
        u1 = x1.y + xr.y + a1 * we.y; u1 = u1 > 0.f ? u1 : SLOPE * u1;
        u2 = x1.z + xr.z + a1 * we.z; u2 = u2 > 0.f ? u2 : SLOPE * u2;
        u3 = x1.w + xr.w + a1 * we.w; u3 = u3 > 0.f ? u3 : SLOPE * u3;
        float p1 = u0 * at.x + u1 * at.y + u2 * at.z + u3 * at.w;
        u0 = x2.x + xr.x + a2 * we.x; u0 = u0 > 0.f ? u0 : SLOPE * u0;
        u1 = x2.y + xr.y + a2 * we.y; u1 = u1 > 0.f ? u1 : SLOPE * u1;
        u2 = x2.z + xr.z + a2 * we.z; u2 = u2 > 0.f ? u2 : SLOPE * u2;
        u3 = x2.w + xr.w + a2 * we.w; u3 = u3 > 0.f ? u3 : SLOPE * u3;
        float p2 = u0 * at.x + u1 * at.y + u2 * at.z + u3 * at.w;
        u0 = x3.x + xr.x + a3 * we.x; u0 = u0 > 0.f ? u0 : SLOPE * u0;
        u1 = x3.y + xr.y + a3 * we.y; u1 = u1 > 0.f ? u1 : SLOPE * u1;
        u2 = x3.z + xr.z + a3 * we.z; u2 = u2 > 0.f ? u2 : SLOPE * u2;
        u3 = x3.w + xr.w + a3 * we.w; u3 = u3 > 0.f ? u3 : SLOPE * u3;
        float p3 = u0 * at.x + u1 * at.y + u2 * at.z + u3 * at.w;
        p0 += __shfl_xor_sync(0xffffffffu, p0, 1);
        p1 += __shfl_xor_sync(0xffffffffu, p1, 1);
        p2 += __shfl_xor_sync(0xffffffffu, p2, 1);
        p3 += __shfl_xor_sync(0xffffffffu, p3, 1);
        p0 += __shfl_xor_sync(0xffffffffu, p0, 2);
        p1 += __shfl_xor_sync(0xffffffffu, p1, 2);
        p2 += __shfl_xor_sync(0xffffffffu, p2, 2);
        p3 += __shfl_xor_sync(0xffffffffu, p3, 2);
        float w0 = __expf(p0), w1 = __expf(p1), w2 = __expf(p2), w3 = __expf(p3);
        denA += w0 + w2; denB += w1 + w3;
        numA.x = fmaf(w0, x0.x, fmaf(w2, x2.x, numA.x));
        numA.y = fmaf(w0, x0.y, fmaf(w2, x2.y, numA.y));
        numA.z = fmaf(w0, x0.z, fmaf(w2, x2.z, numA.z));
        numA.w = fmaf(w0, x0.w, fmaf(w2, x2.w, numA.w));
        numB.x = fmaf(w1, x1.x, fmaf(w3, x3.x, numB.x));
        numB.y = fmaf(w1, x1.y, fmaf(w3, x3.y, numB.y));
        numB.z = fmaf(w1, x1.z, fmaf(w3, x3.z, numB.z));
        numB.w = fmaf(w1, x1.w, fmaf(w3, x3.w, numB.w));
    }
    for (; e < end; e++) {
        int2 er = g_edge[e];
        float a0 = __int_as_float(er.y);
        float4 x0; xl1_load(er.x, c0, x0);
        float u0, u1, u2, u3;
        u0 = x0.x + xr.x + a0 * we.x; u0 = u0 > 0.f ? u0 : SLOPE * u0;
        u1 = x0.y + xr.y + a0 * we.y; u1 = u1 > 0.f ? u1 : SLOPE * u1;
        u2 = x0.z + xr.z + a0 * we.z; u2 = u2 > 0.f ? u2 : SLOPE * u2;
        u3 = x0.w + xr.w + a0 * we.w; u3 = u3 > 0.f ? u3 : SLOPE * u3;
        float p0 = u0 * at.x + u1 * at.y + u2 * at.z + u3 * at.w;
        p0 += __shfl_xor_sync(0xffffffffu, p0, 1);
        p0 += __shfl_xor_sync(0xffffffffu, p0, 2);
        float w0 = __expf(p0);
        denA += w0;
        numA.x = fmaf(w0, x0.x, numA.x); numA.y = fmaf(w0, x0.y, numA.y);
        numA.z = fmaf(w0, x0.z, numA.z); numA.w = fmaf(w0, x0.w, numA.w);
    }
    float inv = 1.f / (denA + denB);
    float4 o = {(numA.x + numB.x) * inv, (numA.y + numB.y) * inv,
                (numA.z + numB.z) * inv, (numA.w + numB.w) * inv};
    *(float4*)(g_out1 + (size_t)n * HID + c0) = o;
    atomicAdd(&ssum[c0 + 0], o.x); atomicAdd(&ssq[c0 + 0], o.x * o.x);
    atomicAdd(&ssum[c0 + 1], o.y); atomicAdd(&ssq[c0 + 1], o.y * o.y);
    atomicAdd(&ssum[c0 + 2], o.z); atomicAdd(&ssq[c0 + 2], o.z * o.z);
    atomicAdd(&ssum[c0 + 3], o.w); atomicAdd(&ssq[c0 + 3], o.w * o.w);
    __syncthreads();
    if (t < HID) { atomicAdd(&g_bnsum[t], ssum[t]); atomicAdd(&g_bnsq[t], ssq[t]); }
}

__global__ void k_agg2(const float* __restrict__ We, const float* __restrict__ att) {
    __shared__ float ssum[EMB], ssq[EMB];
    int t = threadIdx.x;
    if (t < EMB) { ssum[t] = 0.f; ssq[t] = 0.f; }
    __syncthreads();
    int n = (blockIdx.x * blockDim.x + t) >> 5;
    int lane = t & 31;
    int start = g_rowstart[n];
    int end = start + g_ideg[n] + 1;
    int c0 = lane * 2;
    float2 xr = *(const float2*)(g_xr2 + (size_t)n * EMB + c0);
    float2 we = *(const float2*)(We + c0);
    float2 at = *(const float2*)(att + c0);
    float2 numA = {0.f, 0.f}, numB = {0.f, 0.f};
    float denA = 0.f, denB = 0.f;
    int e = start;
    for (; e + 3 < end; e += 4) {
        int2 e0 = g_edge[e], e1 = g_edge[e + 1], e2i = g_edge[e + 2], e3i = g_edge[e + 3];
        float a0 = __int_as_float(e0.y), a1 = __int_as_float(e1.y);
        float a2 = __int_as_float(e2i.y), a3 = __int_as_float(e3i.y);
        float2 x0 = *(const float2*)(g_xl2 + (size_t)e0.x * EMB + c0);
        float2 x1 = *(const float2*)(g_xl2 + (size_t)e1.x * EMB + c0);
        float2 x2 = *(const float2*)(g_xl2 + (size_t)e2i.x * EMB + c0);
        float2 x3 = *(const float2*)(g_xl2 + (size_t)e3i.x * EMB + c0);
        float u0, u1;
        u0 = x0.x + xr.x + a0 * we.x; u0 = u0 > 0.f ? u0 : SLOPE * u0;
        u1 = x0.y + xr.y + a0 * we.y; u1 = u1 > 0.f ? u1 : SLOPE * u1;
        float p0 = u0 * at.x + u1 * at.y;
        u0 = x1.x + xr.x + a1 * we.x; u0 = u0 > 0.f ? u0 : SLOPE * u0;
        u1 = x1.y + xr.y + a1 * we.y; u1 = u1 > 0.f ? u1 : SLOPE * u1;
        float p1 = u0 * at.x + u1 * at.y;
        u0 = x2.x + xr.x + a2 * we.x; u0 = u0 > 0.f ? u0 : SLOPE * u0;
        u1 = x2.y + xr.y + a2 * we.y; u1 = u1 > 0.f ? u1 : SLOPE * u1;
        float p2 = u0 * at.x + u1 * at.y;
        u0 = x3.x + xr.x + a3 * we.x; u0 = u0 > 0.f ? u0 : SLOPE * u0;
        u1 = x3.y + xr.y + a3 * we.y; u1 = u1 > 0.f ? u1 : SLOPE * u1;
        float p3 = u0 * at.x + u1 * at.y;
#pragma unroll
        for (int off = 16; off > 0; off >>= 1) {
            p0 += __shfl_xor_sync(0xffffffffu, p0, off);
            p1 += __shfl_xor_sync(0xffffffffu, p1, off);
            p2 += __shfl_xor_sync(0xffffffffu, p2, off);
            p3 += __shfl_xor_sync(0xffffffffu, p3, off);
        }
        float w0 = __expf(p0), w1 = __expf(p1), w2 = __expf(p2), w3 = __expf(p3);
        denA += w0 + w2; denB += w1 + w3;
        numA.x = fmaf(w0, x0.x, fmaf(w2, x2.x, numA.x));
        numA.y = fmaf(w0, x0.y, fmaf(w2, x2.y, numA.y));
        numB.x = fmaf(w1, x1.x, fmaf(w3, x3.x, numB.x));
        numB.y = fmaf(w1, x1.y, fmaf(w3, x3.y, numB.y));
    }
    for (; e < end; e++) {
        int2 er = g_edge[e];
        float a0 = __int_as_float(er.y);
        float2 x0 = *(const float2*)(g_xl2 + (size_t)er.x * EMB + c0);
        float u0, u1;
        u0 = x0.x + xr.x + a0 * we.x; u0 = u0 > 0.f ? u0 : SLOPE * u0;
        u1 = x0.y + xr.y + a0 * we.y; u1 = u1 > 0.f ? u1 : SLOPE * u1;
        float p0 = u0 * at.x + u1 * at.y;
#pragma unroll
        for (int off = 16; off > 0; off >>= 1)
            p0 += __shfl_xor_sync(0xffffffffu, p0, off);
        float w0 = __expf(p0);
        denA += w0;
        numA.x = fmaf(w0, x0.x, numA.x); numA.y = fmaf(w0, x0.y, numA.y);
    }
    float inv = 1.f / (denA + denB);
    float2 o = {(numA.x + numB.x) * inv, (numA.y + numB.y) * inv};
    *(float2*)(g_out2 + (size_t)n * EMB + c0) = o;
    atomicAdd(&ssum[c0 + 0], o.x); atomicAdd(&ssq[c0 + 0], o.x * o.x);
    atomicAdd(&ssum[c0 + 1], o.y); atomicAdd(&ssq[c0 + 1], o.y * o.y);
    __syncthreads();
    if (t < EMB) { atomicAdd(&g_bnsum2[t], ssum[t]); atomicAdd(&g_bnsq2[t], ssq[t]); }
}

// BN2(inline) + relu + write node_emb + pooled sums
__global__ void k_bnapply2(const float* __restrict__ Yin, float* __restrict__ node_out,
                           const int* __restrict__ batch,
                           const float* __restrict__ gamma, const float* __restrict__ beta) {
    int i = blockIdx.x * blockDim.x + threadIdx.x;
    if (i >= NN * EMB) return;
    int c = i & (EMB - 1);
    int node = i >> 6;
    float mu = g_bnsum2[c] * (1.f / NN);
    float var = g_bnsq2[c] * (1.f / NN) - mu * mu;
    float sc = gamma[c] * rsqrtf(var + EPSV);
    float v = fmaf(Yin[i] - mu, sc, beta[c]);
    v = fmaxf(v, 0.f);
    node_out[i] = v;
    atomicAdd(&g_pool[batch[node] * EMB + c], v);
}

__global__ void k_poollogits(const float* __restrict__ Wc, const float* __restrict__ bc,
                             float* __restrict__ out) {
    int t = threadIdx.x;   // single block, 1024 threads
    for (int i = t; i < GG * EMB; i += blockDim.x) {
        int g = i >> 6;
        float dm = g_pool[i] / fmaxf(g_cnt[g], 1.f);
        g_dom[i] = dm;
        out[NCLS * GG + i] = dm;
    }
    __syncthreads();
    if (t < GG * NCLS) {
        int g = t / NCLS, c = t % NCLS;
        float acc = bc[c];
#pragma unroll 8
        for (int k = 0; k < EMB; k++)
            acc = fmaf(g_dom[g * EMB + k], Wc[k * NCLS + c], acc);
        out[t] = acc;
    }
}

// ---------------- host ----------------
extern "C" void kernel_launch(void* const* d_in, const int* in_sizes, int n_in,
                              void* d_out, int out_size) {
    const float* x     = (const float*)d_in[0];
    const int*   ei    = (const int*)d_in[1];
    const float* eattr = (const float*)d_in[2];
    const int*   batch = (const int*)d_in[3];
    const float* Wl1 = (const float*)d_in[4];  const float* bl1 = (const float*)d_in[5];
    const float* Wr1 = (const float*)d_in[6];  const float* br1 = (const float*)d_in[7];
    const float* We1 = (const float*)d_in[8];  const float* att1 = (const float*)d_in[9];
    // bias1 (d_in[10]) cancels exactly through BN1 -> skipped
    const float* Wl2 = (const float*)d_in[11]; const float* bl2 = (const float*)d_in[12];
    const float* Wr2 = (const float*)d_in[13]; const float* br2 = (const float*)d_in[14];
    const float* We2 = (const float*)d_in[15]; const float* att2 = (const float*)d_in[16];
    // bias2 (d_in[17]) cancels through BN2 -> skipped
    const float* gamma1 = (const float*)d_in[18]; const float* beta1 = (const float*)d_in[19];
    const float* gamma2 = (const float*)d_in[20]; const float* beta2 = (const float*)d_in[21];
    const float* Wc = (const float*)d_in[22]; const float* bc = (const float*)d_in[23];
    float* out = (float*)d_out;

    float *xr1, *out1, *xl2, *xr2, *out2;
    __half* xl1h;
    cudaGetSymbolAddress((void**)&xl1h, g_xl1h);
    cudaGetSymbolAddress((void**)&xr1, g_xr1);
    cudaGetSymbolAddress((void**)&out1, g_out1);
    cudaGetSymbolAddress((void**)&xl2, g_xl2);
    cudaGetSymbolAddress((void**)&xr2, g_xr2);
    cudaGetSymbolAddress((void**)&out2, g_out2);

    const int* src = ei;
    const int* dst = ei + EE;

    bool par = (g_side != nullptr);

    // ---- fork: gemm1 (depends only on inputs) runs concurrent with CSR build ----
    if (par) {
        cudaEventRecord(g_evF, 0);
        cudaStreamWaitEvent(g_side, g_evF, 0);
    }
    k_gemm<FIN, false, true><<<dim3(391, 4), 256, 0, par ? g_side : 0>>>(
        x, Wl1, bl1, nullptr, xl1h, Wr1, br1, xr1, HID, 2, nullptr, nullptr);
    if (par) cudaEventRecord(g_evJ, g_side);

    // ---- CSR build (main stream) ----
    k_zero<<<NB, 256>>>();
    k_hist<<<(EE + 255) / 256, 256>>>(dst, eattr);
    k_scanA<<<NB, 256>>>();
    k_scanB<<<1, 256>>>();
    k_scanC<<<NB, 256>>>(batch);
    k_scatterE<<<(EE + 255) / 256, 256>>>(src, dst, eattr);

    // ---- join ----
    if (par) cudaStreamWaitEvent(0, g_evJ, 0);

    // ---- layer 1 aggregation (+BN1 stats) ----
    k_agg1<<<6250, 256>>>(We1, att1);

    // ---- layer 2 (BN1+relu fused into GEMM X load) ----
    k_gemm<HID, true, false><<<dim3(391, 2), 256>>>(
        out1, Wl2, bl2, xl2, nullptr, Wr2, br2, xr2, EMB, 1, gamma1, beta1);
    k_agg2<<<6250, 256>>>(We2, att2);

    // ---- BN2 + pooling + classifier ----
    k_bnapply2<<<(NN * EMB + 255) / 256, 256>>>(out2, out + NCLS * GG + GG * EMB,
                                                batch, gamma2, beta2);
    k_poollogits<<<1, 1024>>>(Wc, bc, out);
}